// round 2
// baseline (speedup 1.0000x reference)
#include <cuda_runtime.h>
#include <math.h>
#include <stdint.h>

// ---------------- problem constants ----------------
#define Bb   2
#define Tt   2048
#define Dd   2048
#define Hh   32
#define Kd   64
#define CH   128
#define NCH  (Tt / CH)          // 16
#define BT   (Bb * Tt)          // 4096
#define TOK  4
#define EPSV 6.4e-4f            // 1e-5 * 8^2

// ---------------- scratch (device globals, no cudaMalloc) ----------------
__device__ float g_xk[BT * Dd];
__device__ float g_xv[BT * Dd];
__device__ float g_xr[BT * Dd];
__device__ float g_xg[BT * Dd];
__device__ float g_wd[BT * Dd];     // per-token per-channel decay factor in (0,1]
__device__ float g_r [BT * Dd];
__device__ float g_k [BT * Dd];
__device__ float g_v [BT * Dd];
__device__ float g_g [BT * Dd];     // silu-gated
__device__ float g_xout[BT * Dd];   // WKV output pre-groupnorm
__device__ float g_y [BT * Dd];     // groupnorm*gate result
__device__ float g_cs[Bb * Hh * NCH * Kd * Kd];  // per-chunk local states
__device__ float g_es[Bb * Hh * NCH * Kd * Kd];  // entering states per chunk
__device__ float g_ws[Bb * Hh * NCH * Kd];       // per-chunk total decay per k

// =====================================================================
// Kernel A: token mixing. Computes xk,xv,xr,xg scratch + decay g_wd.
// One CTA handles TOK=4 consecutive tokens, 256 threads.
// =====================================================================
__global__ void __launch_bounds__(256) kA(
    const float* __restrict__ x,   const float* __restrict__ shift,
    const float* __restrict__ tmx, const float* __restrict__ tmw,
    const float* __restrict__ tmk, const float* __restrict__ tmv,
    const float* __restrict__ tmr, const float* __restrict__ tmg,
    const float* __restrict__ w1,  const float* __restrict__ w2,
    const float* __restrict__ td,  const float* __restrict__ dw1,
    const float* __restrict__ dw2)
{
    __shared__ float sxxx[TOK][Dd];   // 32 KB; reused for xw after phase 3
    __shared__ float st[TOK][160];    // tanh(xxx @ w1)
    __shared__ float sh[TOK][64];     // tanh(xw @ dw1)

    const int tid = threadIdx.x;
    const int t0  = blockIdx.x * TOK;   // global token index in [0, B*T)

    // ---- phase 1: xxx = x + dxprev * time_maa_x ----
    for (int tok = 0; tok < TOK; tok++) {
        int gt = t0 + tok;
        int b = gt / Tt, tt = gt % Tt;
        const float* xrow = x + (size_t)gt * Dd;
        const float* xprv = (tt == 0) ? (shift + (size_t)b * Dd)
                                      : (x + (size_t)(gt - 1) * Dd);
        for (int d = tid; d < Dd; d += 256) {
            float xv_ = xrow[d];
            float dx  = xprv[d] - xv_;
            sxxx[tok][d] = xv_ + dx * tmx[d];
        }
    }
    __syncthreads();

    // ---- phase 2: st = tanh(xxx @ w1), 160 outputs ----
    if (tid < 160) {
        float acc[TOK];
        #pragma unroll
        for (int t = 0; t < TOK; t++) acc[t] = 0.f;
        for (int d = 0; d < Dd; d++) {
            float w1v = w1[d * 160 + tid];
            #pragma unroll
            for (int t = 0; t < TOK; t++) acc[t] += sxxx[t][d] * w1v;
        }
        #pragma unroll
        for (int t = 0; t < TOK; t++) st[t][tid] = tanhf(acc[t]);
    }
    __syncthreads();

    // ---- phase 3: 5 mixing corrections, write xk/xv/xr/xg, keep xw in smem ----
    for (int d = tid; d < Dd; d += 256) {
        float macc[TOK][5];
        #pragma unroll
        for (int t = 0; t < TOK; t++)
            #pragma unroll
            for (int f = 0; f < 5; f++) macc[t][f] = 0.f;

        for (int j = 0; j < 160; j++) {
            float w2v = w2[(size_t)j * Dd + d];
            int f = j >> 5;
            #pragma unroll
            for (int t = 0; t < TOK; t++) macc[t][f] += st[t][j] * w2v;
        }
        float twv = tmw[d], tkv = tmk[d], tvv = tmv[d], trv = tmr[d], tgv = tmg[d];
        for (int tok = 0; tok < TOK; tok++) {
            int gt = t0 + tok;
            int b = gt / Tt, tt = gt % Tt;
            float xv_ = x[(size_t)gt * Dd + d];
            float xpv = (tt == 0) ? shift[(size_t)b * Dd + d]
                                  : x[(size_t)(gt - 1) * Dd + d];
            float dx = xpv - xv_;
            size_t o = (size_t)gt * Dd + d;
            g_xk[o] = xv_ + dx * (tkv + macc[tok][1]);
            g_xv[o] = xv_ + dx * (tvv + macc[tok][2]);
            g_xr[o] = xv_ + dx * (trv + macc[tok][3]);
            g_xg[o] = xv_ + dx * (tgv + macc[tok][4]);
            sxxx[tok][d] = xv_ + dx * (twv + macc[tok][0]);   // xw
        }
    }
    __syncthreads();

    // ---- phase 4: hidden = tanh(xw @ dw1), 64 outputs per token ----
    {
        int j  = tid & 63;
        int tq = tid >> 6;   // 0..3 -> token within block
        float acc = 0.f;
        for (int d = 0; d < Dd; d++)
            acc += sxxx[tq][d] * dw1[d * 64 + j];
        sh[tq][j] = tanhf(acc);
    }
    __syncthreads();

    // ---- phase 5: w = td + hidden @ dw2 ; wd = clip(exp(-exp(w)), 0.005) ----
    for (int d = tid; d < Dd; d += 256) {
        float acc[TOK];
        #pragma unroll
        for (int t = 0; t < TOK; t++) acc[t] = 0.f;
        for (int j = 0; j < 64; j++) {
            float w2v = dw2[(size_t)j * Dd + d];
            #pragma unroll
            for (int t = 0; t < TOK; t++) acc[t] += sh[t][j] * w2v;
        }
        float tdv = td[d];
        #pragma unroll
        for (int t = 0; t < TOK; t++) {
            float wlin = tdv + acc[t];
            float wdv  = fmaxf(expf(-expf(wlin)), 0.005f);
            g_wd[(size_t)(t0 + t) * Dd + d] = wdv;
        }
    }
}

// =====================================================================
// GEMM: C[m,n] = sum_k A[m,k] * Wm[n,k]   (A:[BT x D], Wm:[D x D] row-major)
// mode 0 = plain, 1 = silu epilogue.
// 128x128 tile, BK=16, 256 threads, 8x8 per-thread microtile.
// =====================================================================
__global__ void __launch_bounds__(256, 2) gemm_nt(
    const float* __restrict__ A, const float* __restrict__ Wm,
    float* __restrict__ C, int mode)
{
    __shared__ float As[16][132];
    __shared__ float Bs[16][132];

    const int tid = threadIdx.x;
    const int m0 = blockIdx.y * 128;
    const int n0 = blockIdx.x * 128;
    const int lr = tid >> 2;          // 0..63
    const int lc = (tid & 3) * 4;     // 0,4,8,12
    const int ty = tid >> 4;          // 0..15
    const int tx = tid & 15;          // 0..15

    float acc[8][8];
    #pragma unroll
    for (int i = 0; i < 8; i++)
        #pragma unroll
        for (int j = 0; j < 8; j++) acc[i][j] = 0.f;

    for (int kt = 0; kt < Dd; kt += 16) {
        #pragma unroll
        for (int i = 0; i < 2; i++) {
            int row = lr + i * 64;
            float4 av = *(const float4*)&A [(size_t)(m0 + row) * Dd + kt + lc];
            float4 bv = *(const float4*)&Wm[(size_t)(n0 + row) * Dd + kt + lc];
            As[lc + 0][row] = av.x; As[lc + 1][row] = av.y;
            As[lc + 2][row] = av.z; As[lc + 3][row] = av.w;
            Bs[lc + 0][row] = bv.x; Bs[lc + 1][row] = bv.y;
            Bs[lc + 2][row] = bv.z; Bs[lc + 3][row] = bv.w;
        }
        __syncthreads();
        #pragma unroll
        for (int k = 0; k < 16; k++) {
            float a[8], b[8];
            *(float4*)&a[0] = *(float4*)&As[k][ty * 8];
            *(float4*)&a[4] = *(float4*)&As[k][ty * 8 + 4];
            *(float4*)&b[0] = *(float4*)&Bs[k][tx * 8];
            *(float4*)&b[4] = *(float4*)&Bs[k][tx * 8 + 4];
            #pragma unroll
            for (int i = 0; i < 8; i++)
                #pragma unroll
                for (int j = 0; j < 8; j++) acc[i][j] += a[i] * b[j];
        }
        __syncthreads();
    }

    #pragma unroll
    for (int i = 0; i < 8; i++) {
        size_t m = (size_t)(m0 + ty * 8 + i);
        float out[8];
        #pragma unroll
        for (int j = 0; j < 8; j++) {
            float v = acc[i][j];
            if (mode == 1) v = v / (1.f + expf(-v));   // silu
            out[j] = v;
        }
        float* cp = &C[m * Dd + n0 + tx * 8];
        *(float4*)&cp[0] = *(float4*)&out[0];
        *(float4*)&cp[4] = *(float4*)&out[4];
    }
}

// =====================================================================
// WKV pass 1: per-chunk local state from zero init + total per-k decay.
// grid = B*H*NCH, 64 threads (thread j owns value-column j).
// Recurrence: S[k][j] = wd[t][k]*S[k][j] + k[t][k]*v[t][j]
// =====================================================================
__global__ void __launch_bounds__(64) wkv_pass1(
    const float* __restrict__ kbuf, const float* __restrict__ vbuf)
{
    const int cid = blockIdx.x;            // (b*H + h)*NCH + n
    const int n  = cid % NCH;
    const int bh = cid / NCH;
    const int h  = bh % Hh;
    const int b  = bh / Hh;
    const int j  = threadIdx.x;

    __shared__ float skk[64], swd[64];
    float S[64];
    #pragma unroll
    for (int k = 0; k < 64; k++) S[k] = 0.f;
    float wsa = 1.f;

    size_t base = ((size_t)(b * Tt + n * CH)) * Dd + h * 64;
    for (int tt = 0; tt < CH; tt++) {
        size_t o = base + (size_t)tt * Dd;
        float kk = kbuf[o + j];
        float wd = g_wd[o + j];
        float vj = vbuf[o + j];
        skk[j] = kk; swd[j] = wd;
        wsa *= wd;
        __syncthreads();
        #pragma unroll
        for (int k = 0; k < 64; k++)
            S[k] = swd[k] * S[k] + skk[k] * vj;
        __syncthreads();
    }
    float* cs = g_cs + (size_t)cid * 4096;
    #pragma unroll
    for (int k = 0; k < 64; k++) cs[k * 64 + j] = S[k];
    g_ws[cid * 64 + j] = wsa;
}

// =====================================================================
// WKV pass 2: scan over chunks -> entering states + final state output.
// grid = B*H, 64 threads.
// =====================================================================
__global__ void __launch_bounds__(64) wkv_pass2(
    const float* __restrict__ state0, float* __restrict__ out_state)
{
    const int bh = blockIdx.x;
    const int j  = threadIdx.x;
    __shared__ float sws[64];

    float S[64];
    const float* s0 = state0 + (size_t)bh * 4096;
    #pragma unroll
    for (int k = 0; k < 64; k++) S[k] = s0[k * 64 + j];

    for (int n = 0; n < NCH; n++) {
        size_t cid = (size_t)bh * NCH + n;
        float* es = g_es + cid * 4096;
        #pragma unroll
        for (int k = 0; k < 64; k++) es[k * 64 + j] = S[k];
        sws[j] = g_ws[cid * 64 + j];
        __syncthreads();
        const float* cs = g_cs + cid * 4096;
        #pragma unroll
        for (int k = 0; k < 64; k++)
            S[k] = S[k] * sws[k] + cs[k * 64 + j];
        __syncthreads();
    }
    float* os = out_state + (size_t)bh * 4096;
    #pragma unroll
    for (int k = 0; k < 64; k++) os[k * 64 + j] = S[k];
}

// =====================================================================
// WKV pass 3: intra-chunk recurrence with entering state, produce x_out.
// out[t][j] = sum_k r[t][k]*(S[k][j] + u[k]*k[t][k]*v[t][j]) ; then update S.
// =====================================================================
__global__ void __launch_bounds__(64) wkv_pass3(
    const float* __restrict__ rbuf, const float* __restrict__ kbuf,
    const float* __restrict__ vbuf, const float* __restrict__ faaaa)
{
    const int cid = blockIdx.x;
    const int n  = cid % NCH;
    const int bh = cid / NCH;
    const int h  = bh % Hh;
    const int b  = bh / Hh;
    const int j  = threadIdx.x;

    __shared__ float skk[64], swd[64], sr[64], su[64];
    float S[64];
    const float* es = g_es + (size_t)cid * 4096;
    #pragma unroll
    for (int k = 0; k < 64; k++) S[k] = es[k * 64 + j];
    su[j] = faaaa[h * 64 + j];

    size_t base = ((size_t)(b * Tt + n * CH)) * Dd + h * 64;
    for (int tt = 0; tt < CH; tt++) {
        size_t o = base + (size_t)tt * Dd;
        skk[j] = kbuf[o + j];
        swd[j] = g_wd[o + j];
        sr[j]  = rbuf[o + j];
        float vj = vbuf[o + j];
        __syncthreads();
        float outv = 0.f;
        #pragma unroll
        for (int k = 0; k < 64; k++) {
            float kv = skk[k] * vj;
            outv += sr[k] * (S[k] + su[k] * kv);
            S[k] = swd[k] * S[k] + kv;
        }
        g_xout[o + j] = outv;
        __syncthreads();
    }
}

// =====================================================================
// GroupNorm (32 groups of 64) * silu-gate. CTA = 1 token, 8 warps x 4 groups.
// =====================================================================
__global__ void __launch_bounds__(256) gn_gate(
    const float* __restrict__ gamma, const float* __restrict__ beta)
{
    const int token = blockIdx.x;
    const int w = threadIdx.x >> 5;
    const int lane = threadIdx.x & 31;

    for (int gq = 0; gq < 4; gq++) {
        int h = w * 4 + gq;
        size_t base = (size_t)token * Dd + h * 64;
        float v0 = g_xout[base + lane];
        float v1 = g_xout[base + 32 + lane];
        float s  = v0 + v1;
        float s2 = v0 * v0 + v1 * v1;
        #pragma unroll
        for (int off = 16; off > 0; off >>= 1) {
            s  += __shfl_xor_sync(0xffffffffu, s,  off);
            s2 += __shfl_xor_sync(0xffffffffu, s2, off);
        }
        float mu  = s * (1.f / 64.f);
        float var = s2 * (1.f / 64.f) - mu * mu;
        float inv = rsqrtf(var + EPSV);
        int d0 = h * 64 + lane;
        float y0 = ((v0 - mu) * inv * gamma[d0]      + beta[d0])      * g_g[base + lane];
        float y1 = ((v1 - mu) * inv * gamma[d0 + 32] + beta[d0 + 32]) * g_g[base + 32 + lane];
        g_y[base + lane]      = y0;
        g_y[base + 32 + lane] = y1;
    }
}

// =====================================================================
// x[:, -1] copy into output region.
// =====================================================================
__global__ void __launch_bounds__(256) xlast_copy(
    const float* __restrict__ x, float* __restrict__ dst)
{
    int i = blockIdx.x * 256 + threadIdx.x;   // < B*D
    int b = i / Dd, d = i % Dd;
    dst[i] = x[((size_t)b * Tt + Tt - 1) * Dd + d];
}

// =====================================================================
// launch
// =====================================================================
extern "C" void kernel_launch(void* const* d_in, const int* in_sizes, int n_in,
                              void* d_out, int out_size)
{
    const float* x      = (const float*)d_in[0];
    const float* shift  = (const float*)d_in[1];
    const float* state0 = (const float*)d_in[2];
    const float* tmx    = (const float*)d_in[3];
    const float* tmw    = (const float*)d_in[4];
    const float* tmk    = (const float*)d_in[5];
    const float* tmv    = (const float*)d_in[6];
    const float* tmr    = (const float*)d_in[7];
    const float* tmg    = (const float*)d_in[8];
    const float* w1     = (const float*)d_in[9];
    const float* w2     = (const float*)d_in[10];
    const float* td     = (const float*)d_in[11];
    const float* dw1    = (const float*)d_in[12];
    const float* dw2    = (const float*)d_in[13];
    const float* faaaa  = (const float*)d_in[14];
    const float* Wr     = (const float*)d_in[15];
    const float* Wk     = (const float*)d_in[16];
    const float* Wv     = (const float*)d_in[17];
    const float* Wg     = (const float*)d_in[18];
    const float* Wo     = (const float*)d_in[19];
    const float* gamma  = (const float*)d_in[20];
    const float* beta   = (const float*)d_in[21];
    float* out = (float*)d_out;

    float *xk, *xv, *xr, *xg, *rb, *kb, *vb, *gb, *yb;
    cudaGetSymbolAddress((void**)&xk, g_xk);
    cudaGetSymbolAddress((void**)&xv, g_xv);
    cudaGetSymbolAddress((void**)&xr, g_xr);
    cudaGetSymbolAddress((void**)&xg, g_xg);
    cudaGetSymbolAddress((void**)&rb, g_r);
    cudaGetSymbolAddress((void**)&kb, g_k);
    cudaGetSymbolAddress((void**)&vb, g_v);
    cudaGetSymbolAddress((void**)&gb, g_g);
    cudaGetSymbolAddress((void**)&yb, g_y);

    const size_t BTD = (size_t)BT * Dd;

    kA<<<BT / TOK, 256>>>(x, shift, tmx, tmw, tmk, tmv, tmr, tmg,
                          w1, w2, td, dw1, dw2);

    dim3 gg(Dd / 128, BT / 128);
    gemm_nt<<<gg, 256>>>(xr, Wr, rb, 0);
    gemm_nt<<<gg, 256>>>(xk, Wk, kb, 0);
    gemm_nt<<<gg, 256>>>(xv, Wv, vb, 0);
    gemm_nt<<<gg, 256>>>(xg, Wg, gb, 1);   // silu

    wkv_pass1<<<Bb * Hh * NCH, 64>>>(kb, vb);
    wkv_pass2<<<Bb * Hh, 64>>>(state0, out + BTD + (size_t)Bb * Dd);
    wkv_pass3<<<Bb * Hh * NCH, 64>>>(rb, kb, vb, faaaa);

    gn_gate<<<BT, 256>>>(gamma, beta);

    gemm_nt<<<gg, 256>>>(yb, Wo, out, 0);

    xlast_copy<<<(Bb * Dd) / 256, 256>>>(x, out + BTD);
}

// round 3
// speedup vs baseline: 1.7106x; 1.7106x over previous
#include <cuda_runtime.h>
#include <cuda_bf16.h>
#include <math.h>
#include <stdint.h>

// ---------------- problem constants ----------------
#define Bb   2
#define Tt   2048
#define Dd   2048
#define Hh   32
#define Kd   64
#define CH   128
#define NCH  (Tt / CH)          // 16
#define BT   (Bb * Tt)          // 4096
#define TOK  4
#define EPSV 6.4e-4f            // 1e-5 * 8^2

// ---------------- scratch (device globals, no cudaMalloc) ----------------
// bf16 hi/lo activation operands
__device__ __nv_bfloat16 g_xkh[BT * Dd], g_xkl[BT * Dd];
__device__ __nv_bfloat16 g_xvh[BT * Dd], g_xvl[BT * Dd];
__device__ __nv_bfloat16 g_xrh[BT * Dd], g_xrl[BT * Dd];
__device__ __nv_bfloat16 g_xgh[BT * Dd], g_xgl[BT * Dd];
__device__ __nv_bfloat16 g_yh [BT * Dd], g_yl [BT * Dd];
// bf16 hi/lo weights (split every launch; cheap)
__device__ __nv_bfloat16 g_Wrh[Dd * Dd], g_Wrl[Dd * Dd];
__device__ __nv_bfloat16 g_Wkh[Dd * Dd], g_Wkl[Dd * Dd];
__device__ __nv_bfloat16 g_Wvh[Dd * Dd], g_Wvl[Dd * Dd];
__device__ __nv_bfloat16 g_Wgh[Dd * Dd], g_Wgl[Dd * Dd];
__device__ __nv_bfloat16 g_Woh[Dd * Dd], g_Wol[Dd * Dd];
// fp32 intermediates
__device__ float g_wd[BT * Dd];     // per-token per-channel decay factor in (0,1]
__device__ float g_r [BT * Dd];
__device__ float g_k [BT * Dd];
__device__ float g_v [BT * Dd];
__device__ float g_g [BT * Dd];     // silu-gated
__device__ float g_xout[BT * Dd];   // WKV output pre-groupnorm
__device__ float g_cs[Bb * Hh * NCH * Kd * Kd];  // per-chunk local states
__device__ float g_es[Bb * Hh * NCH * Kd * Kd];  // entering states per chunk
__device__ float g_ws[Bb * Hh * NCH * Kd];       // per-chunk total decay per k

__device__ __forceinline__ void split_bf16(float v, __nv_bfloat16& h, __nv_bfloat16& l) {
    h = __float2bfloat16(v);
    l = __float2bfloat16(v - __bfloat162float(h));
}

// =====================================================================
// Kernel A: token mixing. Computes xk,xv,xr,xg (bf16 hi/lo) + decay g_wd.
// =====================================================================
__global__ void __launch_bounds__(256) kA(
    const float* __restrict__ x,   const float* __restrict__ shift,
    const float* __restrict__ tmx, const float* __restrict__ tmw,
    const float* __restrict__ tmk, const float* __restrict__ tmv,
    const float* __restrict__ tmr, const float* __restrict__ tmg,
    const float* __restrict__ w1,  const float* __restrict__ w2,
    const float* __restrict__ td,  const float* __restrict__ dw1,
    const float* __restrict__ dw2)
{
    __shared__ float sxxx[TOK][Dd];
    __shared__ float st[TOK][160];
    __shared__ float sh[TOK][64];

    const int tid = threadIdx.x;
    const int t0  = blockIdx.x * TOK;

    for (int tok = 0; tok < TOK; tok++) {
        int gt = t0 + tok;
        int b = gt / Tt, tt = gt % Tt;
        const float* xrow = x + (size_t)gt * Dd;
        const float* xprv = (tt == 0) ? (shift + (size_t)b * Dd)
                                      : (x + (size_t)(gt - 1) * Dd);
        for (int d = tid; d < Dd; d += 256) {
            float xv_ = xrow[d];
            float dx  = xprv[d] - xv_;
            sxxx[tok][d] = xv_ + dx * tmx[d];
        }
    }
    __syncthreads();

    if (tid < 160) {
        float acc[TOK];
        #pragma unroll
        for (int t = 0; t < TOK; t++) acc[t] = 0.f;
        for (int d = 0; d < Dd; d++) {
            float w1v = w1[d * 160 + tid];
            #pragma unroll
            for (int t = 0; t < TOK; t++) acc[t] += sxxx[t][d] * w1v;
        }
        #pragma unroll
        for (int t = 0; t < TOK; t++) st[t][tid] = tanhf(acc[t]);
    }
    __syncthreads();

    for (int d = tid; d < Dd; d += 256) {
        float macc[TOK][5];
        #pragma unroll
        for (int t = 0; t < TOK; t++)
            #pragma unroll
            for (int f = 0; f < 5; f++) macc[t][f] = 0.f;

        for (int j = 0; j < 160; j++) {
            float w2v = w2[(size_t)j * Dd + d];
            int f = j >> 5;
            #pragma unroll
            for (int t = 0; t < TOK; t++) macc[t][f] += st[t][j] * w2v;
        }
        float twv = tmw[d], tkv = tmk[d], tvv = tmv[d], trv = tmr[d], tgv = tmg[d];
        for (int tok = 0; tok < TOK; tok++) {
            int gt = t0 + tok;
            int b = gt / Tt, tt = gt % Tt;
            float xv_ = x[(size_t)gt * Dd + d];
            float xpv = (tt == 0) ? shift[(size_t)b * Dd + d]
                                  : x[(size_t)(gt - 1) * Dd + d];
            float dx = xpv - xv_;
            size_t o = (size_t)gt * Dd + d;
            split_bf16(xv_ + dx * (tkv + macc[tok][1]), g_xkh[o], g_xkl[o]);
            split_bf16(xv_ + dx * (tvv + macc[tok][2]), g_xvh[o], g_xvl[o]);
            split_bf16(xv_ + dx * (trv + macc[tok][3]), g_xrh[o], g_xrl[o]);
            split_bf16(xv_ + dx * (tgv + macc[tok][4]), g_xgh[o], g_xgl[o]);
            sxxx[tok][d] = xv_ + dx * (twv + macc[tok][0]);   // xw
        }
    }
    __syncthreads();

    {
        int j  = tid & 63;
        int tq = tid >> 6;
        float acc = 0.f;
        for (int d = 0; d < Dd; d++)
            acc += sxxx[tq][d] * dw1[d * 64 + j];
        sh[tq][j] = tanhf(acc);
    }
    __syncthreads();

    for (int d = tid; d < Dd; d += 256) {
        float acc[TOK];
        #pragma unroll
        for (int t = 0; t < TOK; t++) acc[t] = 0.f;
        for (int j = 0; j < 64; j++) {
            float w2v = dw2[(size_t)j * Dd + d];
            #pragma unroll
            for (int t = 0; t < TOK; t++) acc[t] += sh[t][j] * w2v;
        }
        float tdv = td[d];
        #pragma unroll
        for (int t = 0; t < TOK; t++) {
            float wlin = tdv + acc[t];
            float wdv  = fmaxf(expf(-expf(wlin)), 0.005f);
            g_wd[(size_t)(t0 + t) * Dd + d] = wdv;
        }
    }
}

// =====================================================================
// Weight split: fp32 -> bf16 hi + bf16 lo residual.
// =====================================================================
__global__ void __launch_bounds__(256) wsplit(
    const float* __restrict__ src, __nv_bfloat16* __restrict__ hi,
    __nv_bfloat16* __restrict__ lo)
{
    int i = (blockIdx.x * 256 + threadIdx.x) * 4;   // covers Dd*Dd
    float4 v = *(const float4*)(src + i);
    __nv_bfloat16 h0, h1, h2, h3, l0, l1, l2, l3;
    split_bf16(v.x, h0, l0); split_bf16(v.y, h1, l1);
    split_bf16(v.z, h2, l2); split_bf16(v.w, h3, l3);
    __nv_bfloat162* hp = (__nv_bfloat162*)(hi + i);
    __nv_bfloat162* lp = (__nv_bfloat162*)(lo + i);
    hp[0] = __nv_bfloat162(h0, h1); hp[1] = __nv_bfloat162(h2, h3);
    lp[0] = __nv_bfloat162(l0, l1); lp[1] = __nv_bfloat162(l2, l3);
}

// =====================================================================
// Tensor-core GEMM: C[m,n] = A[m,:] . W[n,:]   with 3x bf16 split:
//   C = Ah.Wh + Al.Wh + Ah.Wl
// 128x128 CTA tile, BK=32, 8 warps (2x4), mma.sync m16n8k16 bf16.
// mode 1 = silu epilogue.
// =====================================================================
#define LDSM4(r0,r1,r2,r3,addr) \
    asm volatile("ldmatrix.sync.aligned.m8n8.x4.shared.b16 {%0,%1,%2,%3}, [%4];" \
        : "=r"(r0),"=r"(r1),"=r"(r2),"=r"(r3) : "r"(addr))

#define MMA16816(d,a,b) \
    asm volatile("mma.sync.aligned.m16n8k16.row.col.f32.bf16.bf16.f32 " \
        "{%0,%1,%2,%3},{%4,%5,%6,%7},{%8,%9},{%0,%1,%2,%3};" \
        : "+f"(d[0]),"+f"(d[1]),"+f"(d[2]),"+f"(d[3]) \
        : "r"(a[0]),"r"(a[1]),"r"(a[2]),"r"(a[3]),"r"(b[0]),"r"(b[1]))

__global__ void __launch_bounds__(256) gemm3(
    const __nv_bfloat16* __restrict__ Ah, const __nv_bfloat16* __restrict__ Al,
    const __nv_bfloat16* __restrict__ Wh, const __nv_bfloat16* __restrict__ Wl,
    float* __restrict__ C, int mode)
{
    // tile: 128 rows x 32 bf16 = 128 x 64B, XOR swizzle on 16B chunks
    __shared__ char sA[2][8192];
    __shared__ char sB[2][8192];

    const int tid  = threadIdx.x;
    const int lane = tid & 31;
    const int w    = tid >> 5;
    const int wm   = w >> 2;          // 0..1
    const int wn   = w & 3;           // 0..3
    const int m0   = blockIdx.y * 128;
    const int n0   = blockIdx.x * 128;

    // ldmatrix lane-derived offsets
    const int rlo = (lane & 7) + ((lane >> 3) & 1) * 8;
    const int lg  = lane >> 4;        // 0/1 -> k chunk half

    int arow[4], asw[4];
    #pragma unroll
    for (int i = 0; i < 4; i++) {
        int r = wm * 64 + i * 16 + rlo;
        arow[i] = r * 64;
        asw[i]  = (r >> 1) & 3;
    }
    int brow[2], bsw[2];
    #pragma unroll
    for (int jp = 0; jp < 2; jp++) {
        int r = wn * 32 + jp * 16 + rlo;
        brow[jp] = r * 64;
        bsw[jp]  = (r >> 1) & 3;
    }

    uint32_t sa_u = (uint32_t)__cvta_generic_to_shared(sA);
    uint32_t sb_u = (uint32_t)__cvta_generic_to_shared(sB);

    // global->smem chunk mapping (2 chunks / thread / operand)
    const int c0 = tid, c1 = tid + 256;
    const int gr0 = c0 >> 2, gc0 = c0 & 3;
    const int gr1 = c1 >> 2, gc1 = c1 & 3;
    const int sts0 = gr0 * 64 + ((gc0 ^ ((gr0 >> 1) & 3)) << 4);
    const int sts1 = gr1 * 64 + ((gc1 ^ ((gr1 >> 1) & 3)) << 4);

    float acc[4][4][4];
    #pragma unroll
    for (int i = 0; i < 4; i++)
        #pragma unroll
        for (int j = 0; j < 4; j++)
            #pragma unroll
            for (int q = 0; q < 4; q++) acc[i][j][q] = 0.f;

    const int NIT = 3 * (Dd / 32);   // 192

    // --- prologue: load iter 0 ---
    uint4 pa0, pa1, pb0, pb1;
    {
        const __nv_bfloat16* Ap = Ah;
        const __nv_bfloat16* Wp = Wh;
        pa0 = *(const uint4*)(Ap + (size_t)(m0 + gr0) * Dd + gc0 * 8);
        pa1 = *(const uint4*)(Ap + (size_t)(m0 + gr1) * Dd + gc1 * 8);
        pb0 = *(const uint4*)(Wp + (size_t)(n0 + gr0) * Dd + gc0 * 8);
        pb1 = *(const uint4*)(Wp + (size_t)(n0 + gr1) * Dd + gc1 * 8);
    }
    *(uint4*)(sA[0] + sts0) = pa0;
    *(uint4*)(sA[0] + sts1) = pa1;
    *(uint4*)(sB[0] + sts0) = pb0;
    *(uint4*)(sB[0] + sts1) = pb1;
    __syncthreads();

    for (int it = 0; it < NIT; it++) {
        const int buf = it & 1;

        // prefetch next tile to registers
        if (it + 1 < NIT) {
            int nx   = it + 1;
            int pass = nx >> 6;              // 0,1,2
            int kk   = (nx & 63) * 32;
            const __nv_bfloat16* Ap = (pass == 1) ? Al : Ah;
            const __nv_bfloat16* Wp = (pass == 2) ? Wl : Wh;
            pa0 = *(const uint4*)(Ap + (size_t)(m0 + gr0) * Dd + kk + gc0 * 8);
            pa1 = *(const uint4*)(Ap + (size_t)(m0 + gr1) * Dd + kk + gc1 * 8);
            pb0 = *(const uint4*)(Wp + (size_t)(n0 + gr0) * Dd + kk + gc0 * 8);
            pb1 = *(const uint4*)(Wp + (size_t)(n0 + gr1) * Dd + kk + gc1 * 8);
        }

        // compute on current buffer
        uint32_t abase = sa_u + buf * 8192;
        uint32_t bbase = sb_u + buf * 8192;
        #pragma unroll
        for (int ks = 0; ks < 2; ks++) {
            uint32_t a[4][4], b[4][2];
            #pragma unroll
            for (int i = 0; i < 4; i++) {
                uint32_t addr = abase + arow[i] + (((ks * 2 + lg) ^ asw[i]) << 4);
                LDSM4(a[i][0], a[i][1], a[i][2], a[i][3], addr);
            }
            #pragma unroll
            for (int jp = 0; jp < 2; jp++) {
                uint32_t addr = bbase + brow[jp] + (((ks * 2 + lg) ^ bsw[jp]) << 4);
                uint32_t t0, t1, t2, t3;
                LDSM4(t0, t1, t2, t3, addr);
                b[2 * jp][0] = t0; b[2 * jp + 1][0] = t1;
                b[2 * jp][1] = t2; b[2 * jp + 1][1] = t3;
            }
            #pragma unroll
            for (int i = 0; i < 4; i++)
                #pragma unroll
                for (int j = 0; j < 4; j++)
                    MMA16816(acc[i][j], a[i], b[j]);
        }

        // store prefetched tile into other buffer
        if (it + 1 < NIT) {
            char* dA = sA[buf ^ 1];
            char* dB = sB[buf ^ 1];
            *(uint4*)(dA + sts0) = pa0;
            *(uint4*)(dA + sts1) = pa1;
            *(uint4*)(dB + sts0) = pb0;
            *(uint4*)(dB + sts1) = pb1;
        }
        __syncthreads();
    }

    // epilogue
    #pragma unroll
    for (int i = 0; i < 4; i++) {
        int mr = m0 + wm * 64 + i * 16 + (lane >> 2);
        #pragma unroll
        for (int j = 0; j < 4; j++) {
            int nc = n0 + wn * 32 + j * 8 + (lane & 3) * 2;
            float v0 = acc[i][j][0], v1 = acc[i][j][1];
            float v2 = acc[i][j][2], v3 = acc[i][j][3];
            if (mode == 1) {
                v0 = v0 / (1.f + expf(-v0));
                v1 = v1 / (1.f + expf(-v1));
                v2 = v2 / (1.f + expf(-v2));
                v3 = v3 / (1.f + expf(-v3));
            }
            *(float2*)&C[(size_t)mr * Dd + nc]        = make_float2(v0, v1);
            *(float2*)&C[(size_t)(mr + 8) * Dd + nc]  = make_float2(v2, v3);
        }
    }
}

// =====================================================================
// WKV pass 1: per-chunk local state from zero init + total per-k decay.
// =====================================================================
__global__ void __launch_bounds__(64) wkv_pass1(
    const float* __restrict__ kbuf, const float* __restrict__ vbuf)
{
    const int cid = blockIdx.x;
    const int n  = cid % NCH;
    const int bh = cid / NCH;
    const int h  = bh % Hh;
    const int b  = bh / Hh;
    const int j  = threadIdx.x;

    __shared__ float skk[64], swd[64];
    float S[64];
    #pragma unroll
    for (int k = 0; k < 64; k++) S[k] = 0.f;
    float wsa = 1.f;

    size_t base = ((size_t)(b * Tt + n * CH)) * Dd + h * 64;
    for (int tt = 0; tt < CH; tt++) {
        size_t o = base + (size_t)tt * Dd;
        float kk = kbuf[o + j];
        float wd = g_wd[o + j];
        float vj = vbuf[o + j];
        skk[j] = kk; swd[j] = wd;
        wsa *= wd;
        __syncthreads();
        #pragma unroll
        for (int k = 0; k < 64; k++)
            S[k] = swd[k] * S[k] + skk[k] * vj;
        __syncthreads();
    }
    float* cs = g_cs + (size_t)cid * 4096;
    #pragma unroll
    for (int k = 0; k < 64; k++) cs[k * 64 + j] = S[k];
    g_ws[cid * 64 + j] = wsa;
}

// =====================================================================
// WKV pass 2: scan over chunks -> entering states + final state output.
// =====================================================================
__global__ void __launch_bounds__(64) wkv_pass2(
    const float* __restrict__ state0, float* __restrict__ out_state)
{
    const int bh = blockIdx.x;
    const int j  = threadIdx.x;
    __shared__ float sws[64];

    float S[64];
    const float* s0 = state0 + (size_t)bh * 4096;
    #pragma unroll
    for (int k = 0; k < 64; k++) S[k] = s0[k * 64 + j];

    for (int n = 0; n < NCH; n++) {
        size_t cid = (size_t)bh * NCH + n;
        float* es = g_es + cid * 4096;
        #pragma unroll
        for (int k = 0; k < 64; k++) es[k * 64 + j] = S[k];
        sws[j] = g_ws[cid * 64 + j];
        __syncthreads();
        const float* cs = g_cs + cid * 4096;
        #pragma unroll
        for (int k = 0; k < 64; k++)
            S[k] = S[k] * sws[k] + cs[k * 64 + j];
        __syncthreads();
    }
    float* os = out_state + (size_t)bh * 4096;
    #pragma unroll
    for (int k = 0; k < 64; k++) os[k * 64 + j] = S[k];
}

// =====================================================================
// WKV pass 3: intra-chunk recurrence with entering state, produce x_out.
// =====================================================================
__global__ void __launch_bounds__(64) wkv_pass3(
    const float* __restrict__ rbuf, const float* __restrict__ kbuf,
    const float* __restrict__ vbuf, const float* __restrict__ faaaa)
{
    const int cid = blockIdx.x;
    const int n  = cid % NCH;
    const int bh = cid / NCH;
    const int h  = bh % Hh;
    const int b  = bh / Hh;
    const int j  = threadIdx.x;

    __shared__ float skk[64], swd[64], sr[64], su[64];
    float S[64];
    const float* es = g_es + (size_t)cid * 4096;
    #pragma unroll
    for (int k = 0; k < 64; k++) S[k] = es[k * 64 + j];
    su[j] = faaaa[h * 64 + j];

    size_t base = ((size_t)(b * Tt + n * CH)) * Dd + h * 64;
    for (int tt = 0; tt < CH; tt++) {
        size_t o = base + (size_t)tt * Dd;
        skk[j] = kbuf[o + j];
        swd[j] = g_wd[o + j];
        sr[j]  = rbuf[o + j];
        float vj = vbuf[o + j];
        __syncthreads();
        float outv = 0.f;
        #pragma unroll
        for (int k = 0; k < 64; k++) {
            float kv = skk[k] * vj;
            outv += sr[k] * (S[k] + su[k] * kv);
            S[k] = swd[k] * S[k] + kv;
        }
        g_xout[o + j] = outv;
        __syncthreads();
    }
}

// =====================================================================
// GroupNorm (32 groups of 64) * silu-gate -> bf16 hi/lo for output GEMM.
// =====================================================================
__global__ void __launch_bounds__(256) gn_gate(
    const float* __restrict__ gamma, const float* __restrict__ beta)
{
    const int token = blockIdx.x;
    const int w = threadIdx.x >> 5;
    const int lane = threadIdx.x & 31;

    for (int gq = 0; gq < 4; gq++) {
        int h = w * 4 + gq;
        size_t base = (size_t)token * Dd + h * 64;
        float v0 = g_xout[base + lane];
        float v1 = g_xout[base + 32 + lane];
        float s  = v0 + v1;
        float s2 = v0 * v0 + v1 * v1;
        #pragma unroll
        for (int off = 16; off > 0; off >>= 1) {
            s  += __shfl_xor_sync(0xffffffffu, s,  off);
            s2 += __shfl_xor_sync(0xffffffffu, s2, off);
        }
        float mu  = s * (1.f / 64.f);
        float var = s2 * (1.f / 64.f) - mu * mu;
        float inv = rsqrtf(var + EPSV);
        int d0 = h * 64 + lane;
        float y0 = ((v0 - mu) * inv * gamma[d0]      + beta[d0])      * g_g[base + lane];
        float y1 = ((v1 - mu) * inv * gamma[d0 + 32] + beta[d0 + 32]) * g_g[base + 32 + lane];
        split_bf16(y0, g_yh[base + lane],      g_yl[base + lane]);
        split_bf16(y1, g_yh[base + 32 + lane], g_yl[base + 32 + lane]);
    }
}

// =====================================================================
// x[:, -1] copy into output region.
// =====================================================================
__global__ void __launch_bounds__(256) xlast_copy(
    const float* __restrict__ x, float* __restrict__ dst)
{
    int i = blockIdx.x * 256 + threadIdx.x;
    int b = i / Dd, d = i % Dd;
    dst[i] = x[((size_t)b * Tt + Tt - 1) * Dd + d];
}

// =====================================================================
// launch
// =====================================================================
extern "C" void kernel_launch(void* const* d_in, const int* in_sizes, int n_in,
                              void* d_out, int out_size)
{
    const float* x      = (const float*)d_in[0];
    const float* shift  = (const float*)d_in[1];
    const float* state0 = (const float*)d_in[2];
    const float* tmx    = (const float*)d_in[3];
    const float* tmw    = (const float*)d_in[4];
    const float* tmk    = (const float*)d_in[5];
    const float* tmv    = (const float*)d_in[6];
    const float* tmr    = (const float*)d_in[7];
    const float* tmg    = (const float*)d_in[8];
    const float* w1     = (const float*)d_in[9];
    const float* w2     = (const float*)d_in[10];
    const float* td     = (const float*)d_in[11];
    const float* dw1    = (const float*)d_in[12];
    const float* dw2    = (const float*)d_in[13];
    const float* faaaa  = (const float*)d_in[14];
    const float* Wr     = (const float*)d_in[15];
    const float* Wk     = (const float*)d_in[16];
    const float* Wv     = (const float*)d_in[17];
    const float* Wg     = (const float*)d_in[18];
    const float* Wo     = (const float*)d_in[19];
    const float* gamma  = (const float*)d_in[20];
    const float* beta   = (const float*)d_in[21];
    float* out = (float*)d_out;

    __nv_bfloat16 *xkh,*xkl,*xvh,*xvl,*xrh,*xrl,*xgh,*xgl,*yh,*yl;
    __nv_bfloat16 *Wrh,*Wrl,*Wkh,*Wkl,*Wvh,*Wvl,*Wgh,*Wgl,*Woh,*Wol;
    float *rb,*kb,*vb,*gb;
    cudaGetSymbolAddress((void**)&xkh, g_xkh); cudaGetSymbolAddress((void**)&xkl, g_xkl);
    cudaGetSymbolAddress((void**)&xvh, g_xvh); cudaGetSymbolAddress((void**)&xvl, g_xvl);
    cudaGetSymbolAddress((void**)&xrh, g_xrh); cudaGetSymbolAddress((void**)&xrl, g_xrl);
    cudaGetSymbolAddress((void**)&xgh, g_xgh); cudaGetSymbolAddress((void**)&xgl, g_xgl);
    cudaGetSymbolAddress((void**)&yh,  g_yh);  cudaGetSymbolAddress((void**)&yl,  g_yl);
    cudaGetSymbolAddress((void**)&Wrh, g_Wrh); cudaGetSymbolAddress((void**)&Wrl, g_Wrl);
    cudaGetSymbolAddress((void**)&Wkh, g_Wkh); cudaGetSymbolAddress((void**)&Wkl, g_Wkl);
    cudaGetSymbolAddress((void**)&Wvh, g_Wvh); cudaGetSymbolAddress((void**)&Wvl, g_Wvl);
    cudaGetSymbolAddress((void**)&Wgh, g_Wgh); cudaGetSymbolAddress((void**)&Wgl, g_Wgl);
    cudaGetSymbolAddress((void**)&Woh, g_Woh); cudaGetSymbolAddress((void**)&Wol, g_Wol);
    cudaGetSymbolAddress((void**)&rb, g_r);
    cudaGetSymbolAddress((void**)&kb, g_k);
    cudaGetSymbolAddress((void**)&vb, g_v);
    cudaGetSymbolAddress((void**)&gb, g_g);

    const size_t BTD = (size_t)BT * Dd;

    kA<<<BT / TOK, 256>>>(x, shift, tmx, tmw, tmk, tmv, tmr, tmg,
                          w1, w2, td, dw1, dw2);

    const int WG = (Dd * Dd) / (256 * 4);   // 4096 blocks
    wsplit<<<WG, 256>>>(Wr, Wrh, Wrl);
    wsplit<<<WG, 256>>>(Wk, Wkh, Wkl);
    wsplit<<<WG, 256>>>(Wv, Wvh, Wvl);
    wsplit<<<WG, 256>>>(Wg, Wgh, Wgl);
    wsplit<<<WG, 256>>>(Wo, Woh, Wol);

    dim3 gg(Dd / 128, BT / 128);
    gemm3<<<gg, 256>>>(xrh, xrl, Wrh, Wrl, rb, 0);
    gemm3<<<gg, 256>>>(xkh, xkl, Wkh, Wkl, kb, 0);
    gemm3<<<gg, 256>>>(xvh, xvl, Wvh, Wvl, vb, 0);
    gemm3<<<gg, 256>>>(xgh, xgl, Wgh, Wgl, gb, 1);   // silu

    wkv_pass1<<<Bb * Hh * NCH, 64>>>(kb, vb);
    wkv_pass2<<<Bb * Hh, 64>>>(state0, out + BTD + (size_t)Bb * Dd);
    wkv_pass3<<<Bb * Hh * NCH, 64>>>(rb, kb, vb, faaaa);

    gn_gate<<<BT, 256>>>(gamma, beta);

    gemm3<<<gg, 256>>>(yh, yl, Woh, Wol, out, 0);

    xlast_copy<<<(Bb * Dd) / 256, 256>>>(x, out + BTD);
}

// round 5
// speedup vs baseline: 2.1704x; 1.2688x over previous
#include <cuda_runtime.h>
#include <cuda_bf16.h>
#include <math.h>
#include <stdint.h>

// ---------------- problem constants ----------------
#define Bb   2
#define Tt   2048
#define Dd   2048
#define Hh   32
#define Kd   64
#define CH   128
#define NCH  (Tt / CH)          // 16
#define BT   (Bb * Tt)          // 4096
#define TOK  4
#define EPSV 6.4e-4f

// ---------------- scratch (device globals, no cudaMalloc) ----------------
__device__ __nv_bfloat16 g_xkh[BT * Dd], g_xkl[BT * Dd];
__device__ __nv_bfloat16 g_xvh[BT * Dd], g_xvl[BT * Dd];
__device__ __nv_bfloat16 g_xrh[BT * Dd], g_xrl[BT * Dd];
__device__ __nv_bfloat16 g_xgh[BT * Dd], g_xgl[BT * Dd];
__device__ __nv_bfloat16 g_yh [BT * Dd], g_yl [BT * Dd];
__device__ __nv_bfloat16 g_Wrh[Dd * Dd], g_Wrl[Dd * Dd];
__device__ __nv_bfloat16 g_Wkh[Dd * Dd], g_Wkl[Dd * Dd];
__device__ __nv_bfloat16 g_Wvh[Dd * Dd], g_Wvl[Dd * Dd];
__device__ __nv_bfloat16 g_Wgh[Dd * Dd], g_Wgl[Dd * Dd];
__device__ __nv_bfloat16 g_Woh[Dd * Dd], g_Wol[Dd * Dd];
__device__ float g_wd[BT * Dd];
__device__ float g_r [BT * Dd];
__device__ float g_k [BT * Dd];
__device__ float g_v [BT * Dd];
__device__ float g_g [BT * Dd];
__device__ float g_xout[BT * Dd];
__device__ float g_cs[Bb * Hh * NCH * Kd * Kd];
__device__ float g_es[Bb * Hh * NCH * Kd * Kd];
__device__ float g_ws[Bb * Hh * NCH * Kd];

__device__ __forceinline__ void split_bf16(float v, __nv_bfloat16& h, __nv_bfloat16& l) {
    h = __float2bfloat16(v);
    l = __float2bfloat16(v - __bfloat162float(h));
}

// ---------------- PTX helpers ----------------
#define LDSM4(r0,r1,r2,r3,addr) \
    asm volatile("ldmatrix.sync.aligned.m8n8.x4.shared.b16 {%0,%1,%2,%3}, [%4];" \
        : "=r"(r0),"=r"(r1),"=r"(r2),"=r"(r3) : "r"(addr))

#define MMA16816(d,a,b) \
    asm volatile("mma.sync.aligned.m16n8k16.row.col.f32.bf16.bf16.f32 " \
        "{%0,%1,%2,%3},{%4,%5,%6,%7},{%8,%9},{%0,%1,%2,%3};" \
        : "+f"(d[0]),"+f"(d[1]),"+f"(d[2]),"+f"(d[3]) \
        : "r"(a[0]),"r"(a[1]),"r"(a[2]),"r"(a[3]),"r"(b[0]),"r"(b[1]))

#define CP_ASYNC16(dst, src) \
    asm volatile("cp.async.cg.shared.global [%0], [%1], 16;" :: "r"(dst), "l"(src) : "memory")
#define CP_COMMIT() asm volatile("cp.async.commit_group;" ::: "memory")
#define CP_WAIT2()  asm volatile("cp.async.wait_group 2;" ::: "memory")

// =====================================================================
// Tensor-core GEMM (mma.sync), 3x bf16 split: C = Ah.Wh + Al.Wh + Ah.Wl
// 128x128 CTA tile, BK=32, 4-stage cp.async pipeline, 8 warps.
// =====================================================================
#define G_STAGE 16384          // A 8KB + B 8KB per stage
#define G_SMEM  (4 * G_STAGE)  // 64 KB dynamic

__global__ void __launch_bounds__(256) gemm3(
    const __nv_bfloat16* __restrict__ Ah, const __nv_bfloat16* __restrict__ Al,
    const __nv_bfloat16* __restrict__ Wh, const __nv_bfloat16* __restrict__ Wl,
    float* __restrict__ C, int mode)
{
    extern __shared__ char gsm[];
    uint32_t sbase;
    asm("{ .reg .u64 t; cvta.to.shared.u64 t, %1; cvt.u32.u64 %0, t; }"
        : "=r"(sbase) : "l"(gsm));

    const int tid  = threadIdx.x;
    const int lane = tid & 31;
    const int w    = tid >> 5;
    const int wm   = w >> 2;          // 0..1
    const int wn   = w & 3;           // 0..3
    const int m0   = blockIdx.y * 128;
    const int n0   = blockIdx.x * 128;

    const int rlo = (lane & 7) + ((lane >> 3) & 1) * 8;
    const int lg  = lane >> 4;

    int arow[4], asw[4];
    #pragma unroll
    for (int i = 0; i < 4; i++) {
        int r = wm * 64 + i * 16 + rlo;
        arow[i] = r * 64;
        asw[i]  = (r >> 1) & 3;
    }
    int brow[2], bsw[2];
    #pragma unroll
    for (int jp = 0; jp < 2; jp++) {
        int r = wn * 32 + jp * 16 + rlo;
        brow[jp] = r * 64;
        bsw[jp]  = (r >> 1) & 3;
    }

    float acc[4][4][4];
    #pragma unroll
    for (int i = 0; i < 4; i++)
        #pragma unroll
        for (int j = 0; j < 4; j++)
            #pragma unroll
            for (int q = 0; q < 4; q++) acc[i][j][q] = 0.f;

    const int NIT = 3 * (Dd / 32);   // 192

#define ISSUE_CHUNK(nx) do { \
    int _pass = (nx) >> 6; int _kk = ((nx) & 63) << 5; \
    const __nv_bfloat16* _Ap = (_pass == 1) ? Al : Ah; \
    const __nv_bfloat16* _Wp = (_pass == 2) ? Wl : Wh; \
    uint32_t _sa = sbase + ((nx) & 3) * G_STAGE; \
    uint32_t _sb = _sa + 8192; \
    { int r = tid >> 2, c = tid & 3; \
      CP_ASYNC16(_sa + r * 64 + ((c ^ ((r >> 1) & 3)) << 4), \
                 _Ap + (size_t)(m0 + r) * Dd + _kk + c * 8); \
      CP_ASYNC16(_sb + r * 64 + ((c ^ ((r >> 1) & 3)) << 4), \
                 _Wp + (size_t)(n0 + r) * Dd + _kk + c * 8); } \
    { int r = 64 + (tid >> 2), c = tid & 3; \
      CP_ASYNC16(_sa + r * 64 + ((c ^ ((r >> 1) & 3)) << 4), \
                 _Ap + (size_t)(m0 + r) * Dd + _kk + c * 8); \
      CP_ASYNC16(_sb + r * 64 + ((c ^ ((r >> 1) & 3)) << 4), \
                 _Wp + (size_t)(n0 + r) * Dd + _kk + c * 8); } \
} while (0)

    ISSUE_CHUNK(0); CP_COMMIT();
    ISSUE_CHUNK(1); CP_COMMIT();
    ISSUE_CHUNK(2); CP_COMMIT();

    for (int it = 0; it < NIT; it++) {
        CP_WAIT2();
        __syncthreads();

        if (it + 3 < NIT) ISSUE_CHUNK(it + 3);
        CP_COMMIT();

        uint32_t abase = sbase + (it & 3) * G_STAGE;
        uint32_t bbase = abase + 8192;
        #pragma unroll
        for (int ks = 0; ks < 2; ks++) {
            uint32_t a[4][4], b[4][2];
            #pragma unroll
            for (int i = 0; i < 4; i++) {
                uint32_t addr = abase + arow[i] + (((ks * 2 + lg) ^ asw[i]) << 4);
                LDSM4(a[i][0], a[i][1], a[i][2], a[i][3], addr);
            }
            #pragma unroll
            for (int jp = 0; jp < 2; jp++) {
                uint32_t addr = bbase + brow[jp] + (((ks * 2 + lg) ^ bsw[jp]) << 4);
                uint32_t t0, t1, t2, t3;
                LDSM4(t0, t1, t2, t3, addr);
                b[2 * jp][0] = t0; b[2 * jp + 1][0] = t1;
                b[2 * jp][1] = t2; b[2 * jp + 1][1] = t3;
            }
            #pragma unroll
            for (int i = 0; i < 4; i++)
                #pragma unroll
                for (int j = 0; j < 4; j++)
                    MMA16816(acc[i][j], a[i], b[j]);
        }
    }

    // epilogue
    #pragma unroll
    for (int i = 0; i < 4; i++) {
        int mr = m0 + wm * 64 + i * 16 + (lane >> 2);
        #pragma unroll
        for (int j = 0; j < 4; j++) {
            int nc = n0 + wn * 32 + j * 8 + (lane & 3) * 2;
            float v0 = acc[i][j][0], v1 = acc[i][j][1];
            float v2 = acc[i][j][2], v3 = acc[i][j][3];
            if (mode == 1) {
                v0 = v0 / (1.f + expf(-v0));
                v1 = v1 / (1.f + expf(-v1));
                v2 = v2 / (1.f + expf(-v2));
                v3 = v3 / (1.f + expf(-v3));
            }
            *(float2*)&C[(size_t)mr * Dd + nc]       = make_float2(v0, v1);
            *(float2*)&C[(size_t)(mr + 8) * Dd + nc] = make_float2(v2, v3);
        }
    }
}

// =====================================================================
// Kernel A: token mixing. All phases use all 8 warps; no dynamic-indexed
// local arrays (the round-3 version spilled macc[t][f] to local memory).
// dynamic smem: sxxx[4][2048] | ps[8*4*160] | st[4*160] | sh[4*64]
// =====================================================================
#define KA_SMEM ((4*2048 + 8*4*160 + 4*160 + 4*64) * 4)   // 56832 B

__global__ void __launch_bounds__(256) kA(
    const float* __restrict__ x,   const float* __restrict__ shift,
    const float* __restrict__ tmx, const float* __restrict__ tmw,
    const float* __restrict__ tmk, const float* __restrict__ tmv,
    const float* __restrict__ tmr, const float* __restrict__ tmg,
    const float* __restrict__ w1,  const float* __restrict__ w2,
    const float* __restrict__ td,  const float* __restrict__ dw1,
    const float* __restrict__ dw2)
{
    extern __shared__ float sm[];
    float* sxxx = sm;                       // 4*2048
    float* ps   = sm + 4 * 2048;            // 8*4*160
    float* sst  = ps + 8 * 4 * 160;         // 4*160
    float* ssh  = sst + 4 * 160;            // 4*64

    const int tid  = threadIdx.x;
    const int wqid = tid >> 5;
    const int lane = tid & 31;
    const int t0   = blockIdx.x * TOK;

    // ---- phase 1: xxx = x + dxprev * time_maa_x ----
    for (int tok = 0; tok < TOK; tok++) {
        int gt = t0 + tok;
        int b = gt / Tt, tt = gt % Tt;
        const float* xrow = x + (size_t)gt * Dd;
        const float* xprv = (tt == 0) ? (shift + (size_t)b * Dd)
                                      : (x + (size_t)(gt - 1) * Dd);
        for (int d = tid; d < Dd; d += 256) {
            float xv_ = xrow[d];
            sxxx[tok * Dd + d] = xv_ + (xprv[d] - xv_) * tmx[d];
        }
    }
    __syncthreads();

    // ---- phase 2: st = tanh(xxx @ w1); warp w covers d in [w*256, w*256+256) ----
    {
        float acc[5][TOK];
        #pragma unroll
        for (int g = 0; g < 5; g++)
            #pragma unroll
            for (int t = 0; t < TOK; t++) acc[g][t] = 0.f;
        const int d0 = wqid * 256;
        for (int dd = 0; dd < 256; dd++) {
            int d = d0 + dd;
            float xv[TOK];
            #pragma unroll
            for (int t = 0; t < TOK; t++) xv[t] = sxxx[t * Dd + d];
            #pragma unroll
            for (int g = 0; g < 5; g++) {
                float w1v = w1[d * 160 + g * 32 + lane];
                #pragma unroll
                for (int t = 0; t < TOK; t++) acc[g][t] += xv[t] * w1v;
            }
        }
        #pragma unroll
        for (int g = 0; g < 5; g++)
            #pragma unroll
            for (int t = 0; t < TOK; t++)
                ps[(wqid * TOK + t) * 160 + g * 32 + lane] = acc[g][t];
        __syncthreads();
        for (int idx = tid; idx < TOK * 160; idx += 256) {
            int t = idx / 160, j = idx % 160;
            float s = 0.f;
            #pragma unroll
            for (int w8 = 0; w8 < 8; w8++) s += ps[(w8 * TOK + t) * 160 + j];
            sst[t * 160 + j] = tanhf(s);
        }
        __syncthreads();
    }

    // ---- phase 3: mixing corrections (static group index -> registers) ----
    for (int d = tid; d < Dd; d += 256) {
        float macc[TOK][5];
        #pragma unroll
        for (int t = 0; t < TOK; t++)
            #pragma unroll
            for (int g = 0; g < 5; g++) macc[t][g] = 0.f;

        #pragma unroll
        for (int g = 0; g < 5; g++) {
            for (int j32 = 0; j32 < 32; j32++) {
                int j = g * 32 + j32;
                float w2v = w2[(size_t)j * Dd + d];
                #pragma unroll
                for (int t = 0; t < TOK; t++) macc[t][g] += sst[t * 160 + j] * w2v;
            }
        }
        float twv = tmw[d], tkv = tmk[d], tvv = tmv[d], trv = tmr[d], tgv = tmg[d];
        #pragma unroll
        for (int tok = 0; tok < TOK; tok++) {
            int gt = t0 + tok;
            int b = gt / Tt, tt = gt % Tt;
            float xv_ = x[(size_t)gt * Dd + d];
            float xpv = (tt == 0) ? shift[(size_t)b * Dd + d]
                                  : x[(size_t)(gt - 1) * Dd + d];
            float dx = xpv - xv_;
            size_t o = (size_t)gt * Dd + d;
            split_bf16(xv_ + dx * (tkv + macc[tok][1]), g_xkh[o], g_xkl[o]);
            split_bf16(xv_ + dx * (tvv + macc[tok][2]), g_xvh[o], g_xvl[o]);
            split_bf16(xv_ + dx * (trv + macc[tok][3]), g_xrh[o], g_xrl[o]);
            split_bf16(xv_ + dx * (tgv + macc[tok][4]), g_xgh[o], g_xgl[o]);
            sxxx[tok * Dd + d] = xv_ + dx * (twv + macc[tok][0]);   // xw
        }
    }
    __syncthreads();

    // ---- phase 4: hid = tanh(xw @ dw1); warp-parallel split-K ----
    {
        float acc[2][TOK];
        #pragma unroll
        for (int g = 0; g < 2; g++)
            #pragma unroll
            for (int t = 0; t < TOK; t++) acc[g][t] = 0.f;
        const int d0 = wqid * 256;
        for (int dd = 0; dd < 256; dd++) {
            int d = d0 + dd;
            float xv[TOK];
            #pragma unroll
            for (int t = 0; t < TOK; t++) xv[t] = sxxx[t * Dd + d];
            #pragma unroll
            for (int g = 0; g < 2; g++) {
                float w1v = dw1[d * 64 + g * 32 + lane];
                #pragma unroll
                for (int t = 0; t < TOK; t++) acc[g][t] += xv[t] * w1v;
            }
        }
        #pragma unroll
        for (int g = 0; g < 2; g++)
            #pragma unroll
            for (int t = 0; t < TOK; t++)
                ps[(wqid * TOK + t) * 64 + g * 32 + lane] = acc[g][t];
        __syncthreads();
        for (int idx = tid; idx < TOK * 64; idx += 256) {
            int t = idx / 64, j = idx % 64;
            float s = 0.f;
            #pragma unroll
            for (int w8 = 0; w8 < 8; w8++) s += ps[(w8 * TOK + t) * 64 + j];
            ssh[t * 64 + j] = tanhf(s);
        }
        __syncthreads();
    }

    // ---- phase 5: wd = clip(exp(-exp(td + hid @ dw2)), 0.005) ----
    for (int d = tid; d < Dd; d += 256) {
        float acc[TOK];
        #pragma unroll
        for (int t = 0; t < TOK; t++) acc[t] = 0.f;
        for (int j = 0; j < 64; j++) {
            float w2v = dw2[(size_t)j * Dd + d];
            #pragma unroll
            for (int t = 0; t < TOK; t++) acc[t] += ssh[t * 64 + j] * w2v;
        }
        float tdv = td[d];
        #pragma unroll
        for (int t = 0; t < TOK; t++) {
            float wdv = fmaxf(expf(-expf(tdv + acc[t])), 0.005f);
            g_wd[(size_t)(t0 + t) * Dd + d] = wdv;
        }
    }
}

// =====================================================================
// Weight split
// =====================================================================
__global__ void __launch_bounds__(256) wsplit(
    const float* __restrict__ src, __nv_bfloat16* __restrict__ hi,
    __nv_bfloat16* __restrict__ lo)
{
    int i = (blockIdx.x * 256 + threadIdx.x) * 4;
    float4 v = *(const float4*)(src + i);
    __nv_bfloat16 h0, h1, h2, h3, l0, l1, l2, l3;
    split_bf16(v.x, h0, l0); split_bf16(v.y, h1, l1);
    split_bf16(v.z, h2, l2); split_bf16(v.w, h3, l3);
    __nv_bfloat162* hp = (__nv_bfloat162*)(hi + i);
    __nv_bfloat162* lp = (__nv_bfloat162*)(lo + i);
    hp[0] = __nv_bfloat162(h0, h1); hp[1] = __nv_bfloat162(h2, h3);
    lp[0] = __nv_bfloat162(l0, l1); lp[1] = __nv_bfloat162(l2, l3);
}

// =====================================================================
// WKV passes
// =====================================================================
__global__ void __launch_bounds__(64) wkv_pass1(
    const float* __restrict__ kbuf, const float* __restrict__ vbuf)
{
    const int cid = blockIdx.x;
    const int n  = cid % NCH;
    const int bh = cid / NCH;
    const int h  = bh % Hh;
    const int b  = bh / Hh;
    const int j  = threadIdx.x;

    __shared__ float skk[64], swd[64];
    float S[64];
    #pragma unroll
    for (int k = 0; k < 64; k++) S[k] = 0.f;
    float wsa = 1.f;

    size_t base = ((size_t)(b * Tt + n * CH)) * Dd + h * 64;
    for (int tt = 0; tt < CH; tt++) {
        size_t o = base + (size_t)tt * Dd;
        float kk = kbuf[o + j];
        float wd = g_wd[o + j];
        float vj = vbuf[o + j];
        skk[j] = kk; swd[j] = wd;
        wsa *= wd;
        __syncthreads();
        #pragma unroll
        for (int k = 0; k < 64; k++)
            S[k] = swd[k] * S[k] + skk[k] * vj;
        __syncthreads();
    }
    float* cs = g_cs + (size_t)cid * 4096;
    #pragma unroll
    for (int k = 0; k < 64; k++) cs[k * 64 + j] = S[k];
    g_ws[cid * 64 + j] = wsa;
}

__global__ void __launch_bounds__(64) wkv_pass2(
    const float* __restrict__ state0, float* __restrict__ out_state)
{
    const int bh = blockIdx.x;
    const int j  = threadIdx.x;
    __shared__ float sws[64];

    float S[64];
    const float* s0 = state0 + (size_t)bh * 4096;
    #pragma unroll
    for (int k = 0; k < 64; k++) S[k] = s0[k * 64 + j];

    for (int n = 0; n < NCH; n++) {
        size_t cid = (size_t)bh * NCH + n;
        float* es = g_es + cid * 4096;
        #pragma unroll
        for (int k = 0; k < 64; k++) es[k * 64 + j] = S[k];
        sws[j] = g_ws[cid * 64 + j];
        __syncthreads();
        const float* cs = g_cs + cid * 4096;
        #pragma unroll
        for (int k = 0; k < 64; k++)
            S[k] = S[k] * sws[k] + cs[k * 64 + j];
        __syncthreads();
    }
    float* os = out_state + (size_t)bh * 4096;
    #pragma unroll
    for (int k = 0; k < 64; k++) os[k * 64 + j] = S[k];
}

__global__ void __launch_bounds__(64) wkv_pass3(
    const float* __restrict__ rbuf, const float* __restrict__ kbuf,
    const float* __restrict__ vbuf, const float* __restrict__ faaaa)
{
    const int cid = blockIdx.x;
    const int n  = cid % NCH;
    const int bh = cid / NCH;
    const int h  = bh % Hh;
    const int b  = bh / Hh;
    const int j  = threadIdx.x;

    __shared__ float skk[64], swd[64], sr[64], su[64];
    float S[64];
    const float* es = g_es + (size_t)cid * 4096;
    #pragma unroll
    for (int k = 0; k < 64; k++) S[k] = es[k * 64 + j];
    su[j] = faaaa[h * 64 + j];

    size_t base = ((size_t)(b * Tt + n * CH)) * Dd + h * 64;
    for (int tt = 0; tt < CH; tt++) {
        size_t o = base + (size_t)tt * Dd;
        skk[j] = kbuf[o + j];
        swd[j] = g_wd[o + j];
        sr[j]  = rbuf[o + j];
        float vj = vbuf[o + j];
        __syncthreads();
        float outv = 0.f;
        #pragma unroll
        for (int k = 0; k < 64; k++) {
            float kv = skk[k] * vj;
            outv += sr[k] * (S[k] + su[k] * kv);
            S[k] = swd[k] * S[k] + kv;
        }
        g_xout[o + j] = outv;
        __syncthreads();
    }
}

// =====================================================================
// GroupNorm * silu-gate -> bf16 hi/lo
// =====================================================================
__global__ void __launch_bounds__(256) gn_gate(
    const float* __restrict__ gamma, const float* __restrict__ beta)
{
    const int token = blockIdx.x;
    const int w = threadIdx.x >> 5;
    const int lane = threadIdx.x & 31;

    for (int gq = 0; gq < 4; gq++) {
        int h = w * 4 + gq;
        size_t base = (size_t)token * Dd + h * 64;
        float v0 = g_xout[base + lane];
        float v1 = g_xout[base + 32 + lane];
        float s  = v0 + v1;
        float s2 = v0 * v0 + v1 * v1;
        #pragma unroll
        for (int off = 16; off > 0; off >>= 1) {
            s  += __shfl_xor_sync(0xffffffffu, s,  off);
            s2 += __shfl_xor_sync(0xffffffffu, s2, off);
        }
        float mu  = s * (1.f / 64.f);
        float var = s2 * (1.f / 64.f) - mu * mu;
        float inv = rsqrtf(var + EPSV);
        int d0 = h * 64 + lane;
        float y0 = ((v0 - mu) * inv * gamma[d0]      + beta[d0])      * g_g[base + lane];
        float y1 = ((v1 - mu) * inv * gamma[d0 + 32] + beta[d0 + 32]) * g_g[base + 32 + lane];
        split_bf16(y0, g_yh[base + lane],      g_yl[base + lane]);
        split_bf16(y1, g_yh[base + 32 + lane], g_yl[base + 32 + lane]);
    }
}

__global__ void __launch_bounds__(256) xlast_copy(
    const float* __restrict__ x, float* __restrict__ dst)
{
    int i = blockIdx.x * 256 + threadIdx.x;
    int b = i / Dd, d = i % Dd;
    dst[i] = x[((size_t)b * Tt + Tt - 1) * Dd + d];
}

// =====================================================================
// launch
// =====================================================================
extern "C" void kernel_launch(void* const* d_in, const int* in_sizes, int n_in,
                              void* d_out, int out_size)
{
    const float* x      = (const float*)d_in[0];
    const float* shift  = (const float*)d_in[1];
    const float* state0 = (const float*)d_in[2];
    const float* tmx    = (const float*)d_in[3];
    const float* tmw    = (const float*)d_in[4];
    const float* tmk    = (const float*)d_in[5];
    const float* tmv    = (const float*)d_in[6];
    const float* tmr    = (const float*)d_in[7];
    const float* tmg    = (const float*)d_in[8];
    const float* w1     = (const float*)d_in[9];
    const float* w2     = (const float*)d_in[10];
    const float* td     = (const float*)d_in[11];
    const float* dw1    = (const float*)d_in[12];
    const float* dw2    = (const float*)d_in[13];
    const float* faaaa  = (const float*)d_in[14];
    const float* Wr     = (const float*)d_in[15];
    const float* Wk     = (const float*)d_in[16];
    const float* Wv     = (const float*)d_in[17];
    const float* Wg     = (const float*)d_in[18];
    const float* Wo     = (const float*)d_in[19];
    const float* gamma  = (const float*)d_in[20];
    const float* beta   = (const float*)d_in[21];
    float* out = (float*)d_out;

    __nv_bfloat16 *xkh,*xkl,*xvh,*xvl,*xrh,*xrl,*xgh,*xgl,*yh,*yl;
    __nv_bfloat16 *Wrh,*Wrl,*Wkh,*Wkl,*Wvh,*Wvl,*Wgh,*Wgl,*Woh,*Wol;
    float *rb,*kb,*vb,*gb;
    cudaGetSymbolAddress((void**)&xkh, g_xkh); cudaGetSymbolAddress((void**)&xkl, g_xkl);
    cudaGetSymbolAddress((void**)&xvh, g_xvh); cudaGetSymbolAddress((void**)&xvl, g_xvl);
    cudaGetSymbolAddress((void**)&xrh, g_xrh); cudaGetSymbolAddress((void**)&xrl, g_xrl);
    cudaGetSymbolAddress((void**)&xgh, g_xgh); cudaGetSymbolAddress((void**)&xgl, g_xgl);
    cudaGetSymbolAddress((void**)&yh,  g_yh);  cudaGetSymbolAddress((void**)&yl,  g_yl);
    cudaGetSymbolAddress((void**)&Wrh, g_Wrh); cudaGetSymbolAddress((void**)&Wrl, g_Wrl);
    cudaGetSymbolAddress((void**)&Wkh, g_Wkh); cudaGetSymbolAddress((void**)&Wkl, g_Wkl);
    cudaGetSymbolAddress((void**)&Wvh, g_Wvh); cudaGetSymbolAddress((void**)&Wvl, g_Wvl);
    cudaGetSymbolAddress((void**)&Wgh, g_Wgh); cudaGetSymbolAddress((void**)&Wgl, g_Wgl);
    cudaGetSymbolAddress((void**)&Woh, g_Woh); cudaGetSymbolAddress((void**)&Wol, g_Wol);
    cudaGetSymbolAddress((void**)&rb, g_r);
    cudaGetSymbolAddress((void**)&kb, g_k);
    cudaGetSymbolAddress((void**)&vb, g_v);
    cudaGetSymbolAddress((void**)&gb, g_g);

    const size_t BTD = (size_t)BT * Dd;

    static int attr_set = 0;
    if (!attr_set) {
        cudaFuncSetAttribute(gemm3, cudaFuncAttributeMaxDynamicSharedMemorySize, G_SMEM);
        cudaFuncSetAttribute(kA,    cudaFuncAttributeMaxDynamicSharedMemorySize, KA_SMEM);
        attr_set = 1;
    }

    const int WG = (Dd * Dd) / (256 * 4);
    dim3 gg(Dd / 128, BT / 128);

    // launch order chosen so the 6th launch (ncu -s 5 -c 1) is gemm3 (W_r)
    kA<<<BT / TOK, 256, KA_SMEM>>>(x, shift, tmx, tmw, tmk, tmv, tmr, tmg,
                                   w1, w2, td, dw1, dw2);          // 1
    wsplit<<<WG, 256>>>(Wr, Wrh, Wrl);                              // 2
    wsplit<<<WG, 256>>>(Wk, Wkh, Wkl);                              // 3
    wsplit<<<WG, 256>>>(Wv, Wvh, Wvl);                              // 4
    wsplit<<<WG, 256>>>(Wg, Wgh, Wgl);                              // 5
    gemm3<<<gg, 256, G_SMEM>>>(xrh, xrl, Wrh, Wrl, rb, 0);          // 6 <- profiled
    gemm3<<<gg, 256, G_SMEM>>>(xkh, xkl, Wkh, Wkl, kb, 0);
    gemm3<<<gg, 256, G_SMEM>>>(xvh, xvl, Wvh, Wvl, vb, 0);
    gemm3<<<gg, 256, G_SMEM>>>(xgh, xgl, Wgh, Wgl, gb, 1);
    wsplit<<<WG, 256>>>(Wo, Woh, Wol);

    wkv_pass1<<<Bb * Hh * NCH, 64>>>(kb, vb);
    wkv_pass2<<<Bb * Hh, 64>>>(state0, out + BTD + (size_t)Bb * Dd);
    wkv_pass3<<<Bb * Hh * NCH, 64>>>(rb, kb, vb, faaaa);

    gn_gate<<<BT, 256>>>(gamma, beta);

    gemm3<<<gg, 256, G_SMEM>>>(yh, yl, Woh, Wol, out, 0);

    xlast_copy<<<(Bb * Dd) / 256, 256>>>(x, out + BTD);
}

// round 6
// speedup vs baseline: 2.5692x; 1.1837x over previous
#include <cuda_runtime.h>
#include <cuda_bf16.h>
#include <math.h>
#include <stdint.h>

// ---------------- problem constants ----------------
#define Bb   2
#define Tt   2048
#define Dd   2048
#define Hh   32
#define Kd   64
#define CH   128
#define NCH  (Tt / CH)          // 16
#define BT   (Bb * Tt)          // 4096
#define TOK  4
#define EPSV 6.4e-4f

// ---------------- scratch (device globals, no cudaMalloc) ----------------
__device__ __nv_bfloat16 g_xkh[BT * Dd], g_xkl[BT * Dd];
__device__ __nv_bfloat16 g_xvh[BT * Dd], g_xvl[BT * Dd];
__device__ __nv_bfloat16 g_xrh[BT * Dd], g_xrl[BT * Dd];
__device__ __nv_bfloat16 g_xgh[BT * Dd], g_xgl[BT * Dd];
__device__ __nv_bfloat16 g_yh [BT * Dd], g_yl [BT * Dd];
__device__ __nv_bfloat16 g_Wrh[Dd * Dd], g_Wrl[Dd * Dd];
__device__ __nv_bfloat16 g_Wkh[Dd * Dd], g_Wkl[Dd * Dd];
__device__ __nv_bfloat16 g_Wvh[Dd * Dd], g_Wvl[Dd * Dd];
__device__ __nv_bfloat16 g_Wgh[Dd * Dd], g_Wgl[Dd * Dd];
__device__ __nv_bfloat16 g_Woh[Dd * Dd], g_Wol[Dd * Dd];
__device__ float g_wd[BT * Dd];
__device__ float g_r [BT * Dd];
__device__ float g_k [BT * Dd];
__device__ float g_v [BT * Dd];
__device__ float g_g [BT * Dd];
__device__ float g_xout[BT * Dd];
__device__ float g_cs[Bb * Hh * NCH * Kd * Kd];
__device__ float g_es[Bb * Hh * NCH * Kd * Kd];
__device__ float g_ws[Bb * Hh * NCH * Kd];

__device__ __forceinline__ void split_bf16(float v, __nv_bfloat16& h, __nv_bfloat16& l) {
    h = __float2bfloat16(v);
    l = __float2bfloat16(v - __bfloat162float(h));
}

// ---------------- PTX helpers ----------------
#define LDSM4(r0,r1,r2,r3,addr) \
    asm volatile("ldmatrix.sync.aligned.m8n8.x4.shared.b16 {%0,%1,%2,%3}, [%4];" \
        : "=r"(r0),"=r"(r1),"=r"(r2),"=r"(r3) : "r"(addr))

#define MMA16816(d,a,b) \
    asm volatile("mma.sync.aligned.m16n8k16.row.col.f32.bf16.bf16.f32 " \
        "{%0,%1,%2,%3},{%4,%5,%6,%7},{%8,%9},{%0,%1,%2,%3};" \
        : "+f"(d[0]),"+f"(d[1]),"+f"(d[2]),"+f"(d[3]) \
        : "r"(a[0]),"r"(a[1]),"r"(a[2]),"r"(a[3]),"r"(b[0]),"r"(b[1]))

#define CP_ASYNC16(dst, src) \
    asm volatile("cp.async.cg.shared.global [%0], [%1], 16;" :: "r"(dst), "l"(src) : "memory")
#define CP_COMMIT() asm volatile("cp.async.commit_group;" ::: "memory")
#define CP_WAIT1()  asm volatile("cp.async.wait_group 1;" ::: "memory")

// =====================================================================
// Batched tensor-core GEMM (mma.sync), 3x bf16 split per projection:
//   C = Ah.Wh + Al.Wh + Ah.Wl
// 128x128 CTA tile, BK=64, 3-stage cp.async pipeline, 8 warps.
// blockIdx.z selects the projection (up to 4 per launch).
// =====================================================================
#define G_STAGE 32768          // A 16KB + B 16KB per stage
#define G_SMEM  (3 * G_STAGE)  // 96 KB dynamic
#define G_NIT   96             // 3 passes * 32 chunks of BK=64

struct GemmArgs {
    const __nv_bfloat16* Ah[4];
    const __nv_bfloat16* Al[4];
    const __nv_bfloat16* Wh[4];
    const __nv_bfloat16* Wl[4];
    float* C[4];
    int mode[4];
};

__device__ __forceinline__ void issue_chunk(
    int nx, uint32_t sbase, int m0, int n0, int tid,
    const __nv_bfloat16* Ah, const __nv_bfloat16* Al,
    const __nv_bfloat16* Wh, const __nv_bfloat16* Wl)
{
    const int pass = nx >> 5;
    const int kk   = (nx & 31) << 6;
    const __nv_bfloat16* Ap = (pass == 1) ? Al : Ah;
    const __nv_bfloat16* Wp = (pass == 2) ? Wl : Wh;
    uint32_t sa = sbase + (nx % 3) * G_STAGE;
    uint32_t sb = sa + 16384;
    #pragma unroll
    for (int i = 0; i < 4; i++) {
        int ch = tid + i * 256;
        int r = ch >> 3, c = ch & 7;
        uint32_t soff = r * 128 + ((c ^ (r & 7)) << 4);
        CP_ASYNC16(sa + soff, Ap + (size_t)(m0 + r) * Dd + kk + c * 8);
        CP_ASYNC16(sb + soff, Wp + (size_t)(n0 + r) * Dd + kk + c * 8);
    }
}

__global__ void __launch_bounds__(256) gemm4(GemmArgs ga)
{
    extern __shared__ char gsm[];
    uint32_t sbase;
    asm("{ .reg .u64 t; cvta.to.shared.u64 t, %1; cvt.u32.u64 %0, t; }"
        : "=r"(sbase) : "l"(gsm));

    const int z = blockIdx.z;
    const __nv_bfloat16* Ahp = ga.Ah[z];
    const __nv_bfloat16* Alp = ga.Al[z];
    const __nv_bfloat16* Whp = ga.Wh[z];
    const __nv_bfloat16* Wlp = ga.Wl[z];
    float* Cp = ga.C[z];
    const int mode = ga.mode[z];

    const int tid  = threadIdx.x;
    const int lane = tid & 31;
    const int w    = tid >> 5;
    const int wm   = w >> 2;          // 0..1
    const int wn   = w & 3;           // 0..3
    const int m0   = blockIdx.y * 128;
    const int n0   = blockIdx.x * 128;

    const int rlo = (lane & 7) + ((lane >> 3) & 1) * 8;
    const int lg  = lane >> 4;        // 0/1

    int arow[4], asw[4];
    #pragma unroll
    for (int i = 0; i < 4; i++) {
        int r = wm * 64 + i * 16 + rlo;
        arow[i] = r * 128;
        asw[i]  = r & 7;
    }
    int brow[2], bsw[2];
    #pragma unroll
    for (int jp = 0; jp < 2; jp++) {
        int r = wn * 32 + jp * 16 + rlo;
        brow[jp] = r * 128;
        bsw[jp]  = r & 7;
    }

    float acc[4][4][4];
    #pragma unroll
    for (int i = 0; i < 4; i++)
        #pragma unroll
        for (int j = 0; j < 4; j++)
            #pragma unroll
            for (int q = 0; q < 4; q++) acc[i][j][q] = 0.f;

    issue_chunk(0, sbase, m0, n0, tid, Ahp, Alp, Whp, Wlp); CP_COMMIT();
    issue_chunk(1, sbase, m0, n0, tid, Ahp, Alp, Whp, Wlp); CP_COMMIT();

    for (int it = 0; it < G_NIT; it++) {
        CP_WAIT1();
        __syncthreads();

        if (it + 2 < G_NIT)
            issue_chunk(it + 2, sbase, m0, n0, tid, Ahp, Alp, Whp, Wlp);
        CP_COMMIT();

        uint32_t abase = sbase + (it % 3) * G_STAGE;
        uint32_t bbase = abase + 16384;
        #pragma unroll
        for (int ks = 0; ks < 4; ks++) {
            const int cc = ks * 2 + lg;
            uint32_t a[4][4], b[4][2];
            #pragma unroll
            for (int i = 0; i < 4; i++) {
                uint32_t addr = abase + arow[i] + (((cc) ^ asw[i]) << 4);
                LDSM4(a[i][0], a[i][1], a[i][2], a[i][3], addr);
            }
            #pragma unroll
            for (int jp = 0; jp < 2; jp++) {
                uint32_t addr = bbase + brow[jp] + (((cc) ^ bsw[jp]) << 4);
                uint32_t t0, t1, t2, t3;
                LDSM4(t0, t1, t2, t3, addr);
                b[2 * jp][0] = t0; b[2 * jp + 1][0] = t1;
                b[2 * jp][1] = t2; b[2 * jp + 1][1] = t3;
            }
            #pragma unroll
            for (int i = 0; i < 4; i++)
                #pragma unroll
                for (int j = 0; j < 4; j++)
                    MMA16816(acc[i][j], a[i], b[j]);
        }
    }

    // epilogue
    #pragma unroll
    for (int i = 0; i < 4; i++) {
        int mr = m0 + wm * 64 + i * 16 + (lane >> 2);
        #pragma unroll
        for (int j = 0; j < 4; j++) {
            int nc = n0 + wn * 32 + j * 8 + (lane & 3) * 2;
            float v0 = acc[i][j][0], v1 = acc[i][j][1];
            float v2 = acc[i][j][2], v3 = acc[i][j][3];
            if (mode == 1) {
                v0 = v0 / (1.f + expf(-v0));
                v1 = v1 / (1.f + expf(-v1));
                v2 = v2 / (1.f + expf(-v2));
                v3 = v3 / (1.f + expf(-v3));
            }
            *(float2*)&Cp[(size_t)mr * Dd + nc]       = make_float2(v0, v1);
            *(float2*)&Cp[(size_t)(mr + 8) * Dd + nc] = make_float2(v2, v3);
        }
    }
}

// =====================================================================
// Kernel A: token mixing (structure from round 5; no local-array spills)
// =====================================================================
#define KA_SMEM ((4*2048 + 8*4*160 + 4*160 + 4*64) * 4)   // 56832 B

__global__ void __launch_bounds__(256) kA(
    const float* __restrict__ x,   const float* __restrict__ shift,
    const float* __restrict__ tmx, const float* __restrict__ tmw,
    const float* __restrict__ tmk, const float* __restrict__ tmv,
    const float* __restrict__ tmr, const float* __restrict__ tmg,
    const float* __restrict__ w1,  const float* __restrict__ w2,
    const float* __restrict__ td,  const float* __restrict__ dw1,
    const float* __restrict__ dw2)
{
    extern __shared__ float sm[];
    float* sxxx = sm;                       // 4*2048
    float* ps   = sm + 4 * 2048;            // 8*4*160
    float* sst  = ps + 8 * 4 * 160;         // 4*160
    float* ssh  = sst + 4 * 160;            // 4*64

    const int tid  = threadIdx.x;
    const int wqid = tid >> 5;
    const int lane = tid & 31;
    const int t0   = blockIdx.x * TOK;

    for (int tok = 0; tok < TOK; tok++) {
        int gt = t0 + tok;
        int b = gt / Tt, tt = gt % Tt;
        const float* xrow = x + (size_t)gt * Dd;
        const float* xprv = (tt == 0) ? (shift + (size_t)b * Dd)
                                      : (x + (size_t)(gt - 1) * Dd);
        for (int d = tid; d < Dd; d += 256) {
            float xv_ = xrow[d];
            sxxx[tok * Dd + d] = xv_ + (xprv[d] - xv_) * tmx[d];
        }
    }
    __syncthreads();

    {
        float acc[5][TOK];
        #pragma unroll
        for (int g = 0; g < 5; g++)
            #pragma unroll
            for (int t = 0; t < TOK; t++) acc[g][t] = 0.f;
        const int d0 = wqid * 256;
        for (int dd = 0; dd < 256; dd++) {
            int d = d0 + dd;
            float xv[TOK];
            #pragma unroll
            for (int t = 0; t < TOK; t++) xv[t] = sxxx[t * Dd + d];
            #pragma unroll
            for (int g = 0; g < 5; g++) {
                float w1v = w1[d * 160 + g * 32 + lane];
                #pragma unroll
                for (int t = 0; t < TOK; t++) acc[g][t] += xv[t] * w1v;
            }
        }
        #pragma unroll
        for (int g = 0; g < 5; g++)
            #pragma unroll
            for (int t = 0; t < TOK; t++)
                ps[(wqid * TOK + t) * 160 + g * 32 + lane] = acc[g][t];
        __syncthreads();
        for (int idx = tid; idx < TOK * 160; idx += 256) {
            int t = idx / 160, j = idx % 160;
            float s = 0.f;
            #pragma unroll
            for (int w8 = 0; w8 < 8; w8++) s += ps[(w8 * TOK + t) * 160 + j];
            sst[t * 160 + j] = tanhf(s);
        }
        __syncthreads();
    }

    for (int d = tid; d < Dd; d += 256) {
        float macc[TOK][5];
        #pragma unroll
        for (int t = 0; t < TOK; t++)
            #pragma unroll
            for (int g = 0; g < 5; g++) macc[t][g] = 0.f;

        #pragma unroll
        for (int g = 0; g < 5; g++) {
            for (int j32 = 0; j32 < 32; j32++) {
                int j = g * 32 + j32;
                float w2v = w2[(size_t)j * Dd + d];
                #pragma unroll
                for (int t = 0; t < TOK; t++) macc[t][g] += sst[t * 160 + j] * w2v;
            }
        }
        float twv = tmw[d], tkv = tmk[d], tvv = tmv[d], trv = tmr[d], tgv = tmg[d];
        #pragma unroll
        for (int tok = 0; tok < TOK; tok++) {
            int gt = t0 + tok;
            int b = gt / Tt, tt = gt % Tt;
            float xv_ = x[(size_t)gt * Dd + d];
            float xpv = (tt == 0) ? shift[(size_t)b * Dd + d]
                                  : x[(size_t)(gt - 1) * Dd + d];
            float dx = xpv - xv_;
            size_t o = (size_t)gt * Dd + d;
            split_bf16(xv_ + dx * (tkv + macc[tok][1]), g_xkh[o], g_xkl[o]);
            split_bf16(xv_ + dx * (tvv + macc[tok][2]), g_xvh[o], g_xvl[o]);
            split_bf16(xv_ + dx * (trv + macc[tok][3]), g_xrh[o], g_xrl[o]);
            split_bf16(xv_ + dx * (tgv + macc[tok][4]), g_xgh[o], g_xgl[o]);
            sxxx[tok * Dd + d] = xv_ + dx * (twv + macc[tok][0]);
        }
    }
    __syncthreads();

    {
        float acc[2][TOK];
        #pragma unroll
        for (int g = 0; g < 2; g++)
            #pragma unroll
            for (int t = 0; t < TOK; t++) acc[g][t] = 0.f;
        const int d0 = wqid * 256;
        for (int dd = 0; dd < 256; dd++) {
            int d = d0 + dd;
            float xv[TOK];
            #pragma unroll
            for (int t = 0; t < TOK; t++) xv[t] = sxxx[t * Dd + d];
            #pragma unroll
            for (int g = 0; g < 2; g++) {
                float w1v = dw1[d * 64 + g * 32 + lane];
                #pragma unroll
                for (int t = 0; t < TOK; t++) acc[g][t] += xv[t] * w1v;
            }
        }
        #pragma unroll
        for (int g = 0; g < 2; g++)
            #pragma unroll
            for (int t = 0; t < TOK; t++)
                ps[(wqid * TOK + t) * 64 + g * 32 + lane] = acc[g][t];
        __syncthreads();
        for (int idx = tid; idx < TOK * 64; idx += 256) {
            int t = idx / 64, j = idx % 64;
            float s = 0.f;
            #pragma unroll
            for (int w8 = 0; w8 < 8; w8++) s += ps[(w8 * TOK + t) * 64 + j];
            ssh[t * 64 + j] = tanhf(s);
        }
        __syncthreads();
    }

    for (int d = tid; d < Dd; d += 256) {
        float acc[TOK];
        #pragma unroll
        for (int t = 0; t < TOK; t++) acc[t] = 0.f;
        for (int j = 0; j < 64; j++) {
            float w2v = dw2[(size_t)j * Dd + d];
            #pragma unroll
            for (int t = 0; t < TOK; t++) acc[t] += ssh[t * 64 + j] * w2v;
        }
        float tdv = td[d];
        #pragma unroll
        for (int t = 0; t < TOK; t++) {
            float wdv = fmaxf(expf(-expf(tdv + acc[t])), 0.005f);
            g_wd[(size_t)(t0 + t) * Dd + d] = wdv;
        }
    }
}

// =====================================================================
// Weight split: all 5 weights in one launch (blockIdx.y selects)
// =====================================================================
struct SplitArgs {
    const float* s[5];
    __nv_bfloat16* h[5];
    __nv_bfloat16* l[5];
};

__global__ void __launch_bounds__(256) wsplit_all(SplitArgs sa)
{
    const int z = blockIdx.y;
    const float* src = sa.s[z];
    __nv_bfloat16* hi = sa.h[z];
    __nv_bfloat16* lo = sa.l[z];
    int i = (blockIdx.x * 256 + threadIdx.x) * 4;
    float4 v = *(const float4*)(src + i);
    __nv_bfloat16 h0, h1, h2, h3, l0, l1, l2, l3;
    split_bf16(v.x, h0, l0); split_bf16(v.y, h1, l1);
    split_bf16(v.z, h2, l2); split_bf16(v.w, h3, l3);
    __nv_bfloat162* hp = (__nv_bfloat162*)(hi + i);
    __nv_bfloat162* lp = (__nv_bfloat162*)(lo + i);
    hp[0] = __nv_bfloat162(h0, h1); hp[1] = __nv_bfloat162(h2, h3);
    lp[0] = __nv_bfloat162(l0, l1); lp[1] = __nv_bfloat162(l2, l3);
}

// =====================================================================
// WKV pass 1: per-chunk local state; float2-packed smem operands
// =====================================================================
__global__ void __launch_bounds__(64) wkv_pass1(
    const float* __restrict__ kbuf, const float* __restrict__ vbuf)
{
    const int cid = blockIdx.x;
    const int n  = cid % NCH;
    const int bh = cid / NCH;
    const int h  = bh % Hh;
    const int b  = bh / Hh;
    const int j  = threadIdx.x;

    __shared__ float2 sp[64];
    float S[64];
    #pragma unroll
    for (int k = 0; k < 64; k++) S[k] = 0.f;
    float wsa = 1.f;

    size_t base = ((size_t)(b * Tt + n * CH)) * Dd + h * 64;
    for (int tt = 0; tt < CH; tt++) {
        size_t o = base + (size_t)tt * Dd;
        float kk = kbuf[o + j];
        float wd = g_wd[o + j];
        float vj = vbuf[o + j];
        sp[j] = make_float2(kk, wd);
        wsa *= wd;
        __syncthreads();
        const float4* p4 = (const float4*)sp;
        #pragma unroll
        for (int kq = 0; kq < 32; kq++) {
            float4 q = p4[kq];
            S[2 * kq]     = q.y * S[2 * kq]     + q.x * vj;
            S[2 * kq + 1] = q.w * S[2 * kq + 1] + q.z * vj;
        }
        __syncthreads();
    }
    float* cs = g_cs + (size_t)cid * 4096;
    #pragma unroll
    for (int k = 0; k < 64; k++) cs[k * 64 + j] = S[k];
    g_ws[cid * 64 + j] = wsa;
}

// =====================================================================
// WKV pass 2: scan over chunks
// =====================================================================
__global__ void __launch_bounds__(64) wkv_pass2(
    const float* __restrict__ state0, float* __restrict__ out_state)
{
    const int bh = blockIdx.x;
    const int j  = threadIdx.x;
    __shared__ float sws[64];

    float S[64];
    const float* s0 = state0 + (size_t)bh * 4096;
    #pragma unroll
    for (int k = 0; k < 64; k++) S[k] = s0[k * 64 + j];

    for (int n = 0; n < NCH; n++) {
        size_t cid = (size_t)bh * NCH + n;
        float* es = g_es + cid * 4096;
        #pragma unroll
        for (int k = 0; k < 64; k++) es[k * 64 + j] = S[k];
        sws[j] = g_ws[cid * 64 + j];
        __syncthreads();
        const float* cs = g_cs + cid * 4096;
        #pragma unroll
        for (int k = 0; k < 64; k++)
            S[k] = S[k] * sws[k] + cs[k * 64 + j];
        __syncthreads();
    }
    float* os = out_state + (size_t)bh * 4096;
    #pragma unroll
    for (int k = 0; k < 64; k++) os[k * 64 + j] = S[k];
}

// =====================================================================
// WKV pass 3: intra-chunk recurrence; float4-packed smem quads
//   quad[k] = { k_k, wd_k, r_k, r_k*u_k*k_k }
//   out_j = sum_k r_k*S[k][j] + v_j * sum_k (r_k*u_k*k_k)
// =====================================================================
__global__ void __launch_bounds__(64) wkv_pass3(
    const float* __restrict__ rbuf, const float* __restrict__ kbuf,
    const float* __restrict__ vbuf, const float* __restrict__ faaaa)
{
    const int cid = blockIdx.x;
    const int n  = cid % NCH;
    const int bh = cid / NCH;
    const int h  = bh % Hh;
    const int b  = bh / Hh;
    const int j  = threadIdx.x;

    __shared__ float4 sq[64];
    float S[64];
    const float* es = g_es + (size_t)cid * 4096;
    #pragma unroll
    for (int k = 0; k < 64; k++) S[k] = es[k * 64 + j];
    const float uj = faaaa[h * 64 + j];

    size_t base = ((size_t)(b * Tt + n * CH)) * Dd + h * 64;
    for (int tt = 0; tt < CH; tt++) {
        size_t o = base + (size_t)tt * Dd;
        float kk = kbuf[o + j];
        float wd = g_wd[o + j];
        float rr = rbuf[o + j];
        float vj = vbuf[o + j];
        sq[j] = make_float4(kk, wd, rr, rr * uj * kk);
        __syncthreads();
        float outv = 0.f, rk = 0.f;
        #pragma unroll
        for (int k = 0; k < 64; k++) {
            float4 q = sq[k];
            outv += q.z * S[k];
            rk   += q.w;
            S[k] = q.y * S[k] + q.x * vj;
        }
        g_xout[o + j] = outv + rk * vj;
        __syncthreads();
    }
}

// =====================================================================
// GroupNorm * silu-gate -> bf16 hi/lo
// =====================================================================
__global__ void __launch_bounds__(256) gn_gate(
    const float* __restrict__ gamma, const float* __restrict__ beta)
{
    const int token = blockIdx.x;
    const int w = threadIdx.x >> 5;
    const int lane = threadIdx.x & 31;

    for (int gq = 0; gq < 4; gq++) {
        int h = w * 4 + gq;
        size_t base = (size_t)token * Dd + h * 64;
        float v0 = g_xout[base + lane];
        float v1 = g_xout[base + 32 + lane];
        float s  = v0 + v1;
        float s2 = v0 * v0 + v1 * v1;
        #pragma unroll
        for (int off = 16; off > 0; off >>= 1) {
            s  += __shfl_xor_sync(0xffffffffu, s,  off);
            s2 += __shfl_xor_sync(0xffffffffu, s2, off);
        }
        float mu  = s * (1.f / 64.f);
        float var = s2 * (1.f / 64.f) - mu * mu;
        float inv = rsqrtf(var + EPSV);
        int d0 = h * 64 + lane;
        float y0 = ((v0 - mu) * inv * gamma[d0]      + beta[d0])      * g_g[base + lane];
        float y1 = ((v1 - mu) * inv * gamma[d0 + 32] + beta[d0 + 32]) * g_g[base + 32 + lane];
        split_bf16(y0, g_yh[base + lane],      g_yl[base + lane]);
        split_bf16(y1, g_yh[base + 32 + lane], g_yl[base + 32 + lane]);
    }
}

__global__ void __launch_bounds__(256) xlast_copy(
    const float* __restrict__ x, float* __restrict__ dst)
{
    int i = blockIdx.x * 256 + threadIdx.x;
    int b = i / Dd, d = i % Dd;
    dst[i] = x[((size_t)b * Tt + Tt - 1) * Dd + d];
}

// =====================================================================
// launch
// =====================================================================
extern "C" void kernel_launch(void* const* d_in, const int* in_sizes, int n_in,
                              void* d_out, int out_size)
{
    const float* x      = (const float*)d_in[0];
    const float* shift  = (const float*)d_in[1];
    const float* state0 = (const float*)d_in[2];
    const float* tmx    = (const float*)d_in[3];
    const float* tmw    = (const float*)d_in[4];
    const float* tmk    = (const float*)d_in[5];
    const float* tmv    = (const float*)d_in[6];
    const float* tmr    = (const float*)d_in[7];
    const float* tmg    = (const float*)d_in[8];
    const float* w1     = (const float*)d_in[9];
    const float* w2     = (const float*)d_in[10];
    const float* td     = (const float*)d_in[11];
    const float* dw1    = (const float*)d_in[12];
    const float* dw2    = (const float*)d_in[13];
    const float* faaaa  = (const float*)d_in[14];
    const float* Wr     = (const float*)d_in[15];
    const float* Wk     = (const float*)d_in[16];
    const float* Wv     = (const float*)d_in[17];
    const float* Wg     = (const float*)d_in[18];
    const float* Wo     = (const float*)d_in[19];
    const float* gamma  = (const float*)d_in[20];
    const float* beta   = (const float*)d_in[21];
    float* out = (float*)d_out;

    __nv_bfloat16 *xkh,*xkl,*xvh,*xvl,*xrh,*xrl,*xgh,*xgl,*yh,*yl;
    __nv_bfloat16 *Wrh,*Wrl,*Wkh,*Wkl,*Wvh,*Wvl,*Wgh,*Wgl,*Woh,*Wol;
    float *rb,*kb,*vb,*gb;
    cudaGetSymbolAddress((void**)&xkh, g_xkh); cudaGetSymbolAddress((void**)&xkl, g_xkl);
    cudaGetSymbolAddress((void**)&xvh, g_xvh); cudaGetSymbolAddress((void**)&xvl, g_xvl);
    cudaGetSymbolAddress((void**)&xrh, g_xrh); cudaGetSymbolAddress((void**)&xrl, g_xrl);
    cudaGetSymbolAddress((void**)&xgh, g_xgh); cudaGetSymbolAddress((void**)&xgl, g_xgl);
    cudaGetSymbolAddress((void**)&yh,  g_yh);  cudaGetSymbolAddress((void**)&yl,  g_yl);
    cudaGetSymbolAddress((void**)&Wrh, g_Wrh); cudaGetSymbolAddress((void**)&Wrl, g_Wrl);
    cudaGetSymbolAddress((void**)&Wkh, g_Wkh); cudaGetSymbolAddress((void**)&Wkl, g_Wkl);
    cudaGetSymbolAddress((void**)&Wvh, g_Wvh); cudaGetSymbolAddress((void**)&Wvl, g_Wvl);
    cudaGetSymbolAddress((void**)&Wgh, g_Wgh); cudaGetSymbolAddress((void**)&Wgl, g_Wgl);
    cudaGetSymbolAddress((void**)&Woh, g_Woh); cudaGetSymbolAddress((void**)&Wol, g_Wol);
    cudaGetSymbolAddress((void**)&rb, g_r);
    cudaGetSymbolAddress((void**)&kb, g_k);
    cudaGetSymbolAddress((void**)&vb, g_v);
    cudaGetSymbolAddress((void**)&gb, g_g);

    const size_t BTD = (size_t)BT * Dd;

    cudaFuncSetAttribute(gemm4, cudaFuncAttributeMaxDynamicSharedMemorySize, G_SMEM);
    cudaFuncSetAttribute(kA,    cudaFuncAttributeMaxDynamicSharedMemorySize, KA_SMEM);

    // ---- 0: weight split (all 5) ----
    SplitArgs sa;
    sa.s[0] = Wr; sa.h[0] = Wrh; sa.l[0] = Wrl;
    sa.s[1] = Wk; sa.h[1] = Wkh; sa.l[1] = Wkl;
    sa.s[2] = Wv; sa.h[2] = Wvh; sa.l[2] = Wvl;
    sa.s[3] = Wg; sa.h[3] = Wgh; sa.l[3] = Wgl;
    sa.s[4] = Wo; sa.h[4] = Woh; sa.l[4] = Wol;
    dim3 wsg((Dd * Dd) / (256 * 4), 5);
    wsplit_all<<<wsg, 256>>>(sa);

    // ---- 1: token mixing ----
    kA<<<BT / TOK, 256, KA_SMEM>>>(x, shift, tmx, tmw, tmk, tmv, tmr, tmg,
                                   w1, w2, td, dw1, dw2);

    // ---- 2: x last ----
    xlast_copy<<<(Bb * Dd) / 256, 256>>>(x, out + BTD);

    // ---- 3,4: projection GEMMs (2 x 2 batched) ----
    GemmArgs g1;
    g1.Ah[0] = xrh; g1.Al[0] = xrl; g1.Wh[0] = Wrh; g1.Wl[0] = Wrl; g1.C[0] = rb; g1.mode[0] = 0;
    g1.Ah[1] = xkh; g1.Al[1] = xkl; g1.Wh[1] = Wkh; g1.Wl[1] = Wkl; g1.C[1] = kb; g1.mode[1] = 0;
    GemmArgs g2;
    g2.Ah[0] = xvh; g2.Al[0] = xvl; g2.Wh[0] = Wvh; g2.Wl[0] = Wvl; g2.C[0] = vb; g2.mode[0] = 0;
    g2.Ah[1] = xgh; g2.Al[1] = xgl; g2.Wh[1] = Wgh; g2.Wl[1] = Wgl; g2.C[1] = gb; g2.mode[1] = 1;
    dim3 gg(Dd / 128, BT / 128, 2);
    gemm4<<<gg, 256, G_SMEM>>>(g1);
    gemm4<<<gg, 256, G_SMEM>>>(g2);

    // ---- 5,6,7: WKV ----
    wkv_pass1<<<Bb * Hh * NCH, 64>>>(kb, vb);
    wkv_pass2<<<Bb * Hh, 64>>>(state0, out + BTD + (size_t)Bb * Dd);
    wkv_pass3<<<Bb * Hh * NCH, 64>>>(rb, kb, vb, faaaa);

    // ---- 8: groupnorm * gate ----
    gn_gate<<<BT, 256>>>(gamma, beta);

    // ---- 9: output GEMM ----
    GemmArgs g3;
    g3.Ah[0] = yh; g3.Al[0] = yl; g3.Wh[0] = Woh; g3.Wl[0] = Wol; g3.C[0] = out; g3.mode[0] = 0;
    dim3 go(Dd / 128, BT / 128, 1);
    gemm4<<<go, 256, G_SMEM>>>(g3);
}

// round 7
// speedup vs baseline: 3.2676x; 1.2719x over previous
#include <cuda_runtime.h>
#include <cuda_fp16.h>
#include <math.h>
#include <stdint.h>

// ---------------- problem constants ----------------
#define Bb   2
#define Tt   2048
#define Dd   2048
#define Hh   32
#define Kd   64
#define CH   128
#define NCH  (Tt / CH)          // 16
#define BT   (Bb * Tt)          // 4096
#define TOK  4
#define EPSV 6.4e-4f

// ---------------- scratch (device globals, no cudaMalloc) ----------------
// fp16 hi/lo activations; fp16 hi-only weights
__device__ __half g_xkh[BT * Dd], g_xkl[BT * Dd];
__device__ __half g_xvh[BT * Dd], g_xvl[BT * Dd];
__device__ __half g_xrh[BT * Dd], g_xrl[BT * Dd];
__device__ __half g_xgh[BT * Dd], g_xgl[BT * Dd];
__device__ __half g_yh [BT * Dd], g_yl [BT * Dd];
__device__ __half g_Wrh[Dd * Dd];
__device__ __half g_Wkh[Dd * Dd];
__device__ __half g_Wvh[Dd * Dd];
__device__ __half g_Wgh[Dd * Dd];
__device__ __half g_Woh[Dd * Dd];
__device__ float g_wd[BT * Dd];
__device__ float g_r [BT * Dd];
__device__ float g_k [BT * Dd];
__device__ float g_v [BT * Dd];
__device__ float g_g [BT * Dd];
__device__ float g_xout[BT * Dd];
__device__ float g_cs[Bb * Hh * NCH * Kd * Kd];
__device__ float g_es[Bb * Hh * NCH * Kd * Kd];
__device__ float g_ws[Bb * Hh * NCH * Kd];

__device__ __forceinline__ void split_fp16(float v, __half& h, __half& l) {
    h = __float2half_rn(v);
    l = __float2half_rn(v - __half2float(h));
}

// ---------------- PTX helpers ----------------
#define LDSM4(r0,r1,r2,r3,addr) \
    asm volatile("ldmatrix.sync.aligned.m8n8.x4.shared.b16 {%0,%1,%2,%3}, [%4];" \
        : "=r"(r0),"=r"(r1),"=r"(r2),"=r"(r3) : "r"(addr))

#define MMA16816F(d,a,b) \
    asm volatile("mma.sync.aligned.m16n8k16.row.col.f32.f16.f16.f32 " \
        "{%0,%1,%2,%3},{%4,%5,%6,%7},{%8,%9},{%0,%1,%2,%3};" \
        : "+f"(d[0]),"+f"(d[1]),"+f"(d[2]),"+f"(d[3]) \
        : "r"(a[0]),"r"(a[1]),"r"(a[2]),"r"(a[3]),"r"(b[0]),"r"(b[1]))

#define CP_ASYNC16(dst, src) \
    asm volatile("cp.async.cg.shared.global [%0], [%1], 16;" :: "r"(dst), "l"(src) : "memory")
#define CP_COMMIT() asm volatile("cp.async.commit_group;" ::: "memory")
#define CP_WAIT1()  asm volatile("cp.async.wait_group 1;" ::: "memory")

// =====================================================================
// Batched tensor-core GEMM (mma.sync), 2x fp16 split per projection:
//   C = Ah.Wh + Al.Wh   (= A.Wh exactly; error = A.(W-Wh) ~ 2^-12)
// 128x128 CTA tile, BK=64, 3-stage cp.async pipeline, 8 warps.
// blockIdx.z selects the projection.
// =====================================================================
#define G_STAGE 32768          // A 16KB + B 16KB per stage
#define G_SMEM  (3 * G_STAGE)  // 96 KB dynamic
#define G_NIT   64             // 2 passes * 32 chunks of BK=64

struct GemmArgs {
    const __half* Ah[4];
    const __half* Al[4];
    const __half* Wh[4];
    float* C[4];
    int mode[4];
};

__device__ __forceinline__ void issue_chunk(
    int nx, uint32_t sbase, int m0, int n0, int tid,
    const __half* Ah, const __half* Al, const __half* Wh)
{
    const int pass = nx >> 5;             // 0: Ah, 1: Al
    const int kk   = (nx & 31) << 6;
    const __half* Ap = pass ? Al : Ah;
    uint32_t sa = sbase + (nx % 3) * G_STAGE;
    uint32_t sb = sa + 16384;
    #pragma unroll
    for (int i = 0; i < 4; i++) {
        int ch = tid + i * 256;
        int r = ch >> 3, c = ch & 7;
        uint32_t soff = r * 128 + ((c ^ (r & 7)) << 4);
        CP_ASYNC16(sa + soff, Ap + (size_t)(m0 + r) * Dd + kk + c * 8);
        CP_ASYNC16(sb + soff, Wh + (size_t)(n0 + r) * Dd + kk + c * 8);
    }
}

__global__ void __launch_bounds__(256) gemm4(GemmArgs ga)
{
    extern __shared__ char gsm[];
    uint32_t sbase;
    asm("{ .reg .u64 t; cvta.to.shared.u64 t, %1; cvt.u32.u64 %0, t; }"
        : "=r"(sbase) : "l"(gsm));

    const int z = blockIdx.z;
    const __half* Ahp = ga.Ah[z];
    const __half* Alp = ga.Al[z];
    const __half* Whp = ga.Wh[z];
    float* Cp = ga.C[z];
    const int mode = ga.mode[z];

    const int tid  = threadIdx.x;
    const int lane = tid & 31;
    const int w    = tid >> 5;
    const int wm   = w >> 2;          // 0..1
    const int wn   = w & 3;           // 0..3
    const int m0   = blockIdx.y * 128;
    const int n0   = blockIdx.x * 128;

    const int rlo = (lane & 7) + ((lane >> 3) & 1) * 8;
    const int lg  = lane >> 4;        // 0/1

    int arow[4], asw[4];
    #pragma unroll
    for (int i = 0; i < 4; i++) {
        int r = wm * 64 + i * 16 + rlo;
        arow[i] = r * 128;
        asw[i]  = r & 7;
    }
    int brow[2], bsw[2];
    #pragma unroll
    for (int jp = 0; jp < 2; jp++) {
        int r = wn * 32 + jp * 16 + rlo;
        brow[jp] = r * 128;
        bsw[jp]  = r & 7;
    }

    float acc[4][4][4];
    #pragma unroll
    for (int i = 0; i < 4; i++)
        #pragma unroll
        for (int j = 0; j < 4; j++)
            #pragma unroll
            for (int q = 0; q < 4; q++) acc[i][j][q] = 0.f;

    issue_chunk(0, sbase, m0, n0, tid, Ahp, Alp, Whp); CP_COMMIT();
    issue_chunk(1, sbase, m0, n0, tid, Ahp, Alp, Whp); CP_COMMIT();

    for (int it = 0; it < G_NIT; it++) {
        CP_WAIT1();
        __syncthreads();

        if (it + 2 < G_NIT)
            issue_chunk(it + 2, sbase, m0, n0, tid, Ahp, Alp, Whp);
        CP_COMMIT();

        uint32_t abase = sbase + (it % 3) * G_STAGE;
        uint32_t bbase = abase + 16384;
        #pragma unroll
        for (int ks = 0; ks < 4; ks++) {
            const int cc = ks * 2 + lg;
            uint32_t a[4][4], b[4][2];
            #pragma unroll
            for (int i = 0; i < 4; i++) {
                uint32_t addr = abase + arow[i] + ((cc ^ asw[i]) << 4);
                LDSM4(a[i][0], a[i][1], a[i][2], a[i][3], addr);
            }
            #pragma unroll
            for (int jp = 0; jp < 2; jp++) {
                uint32_t addr = bbase + brow[jp] + ((cc ^ bsw[jp]) << 4);
                uint32_t t0, t1, t2, t3;
                LDSM4(t0, t1, t2, t3, addr);
                b[2 * jp][0] = t0; b[2 * jp + 1][0] = t1;
                b[2 * jp][1] = t2; b[2 * jp + 1][1] = t3;
            }
            #pragma unroll
            for (int i = 0; i < 4; i++)
                #pragma unroll
                for (int j = 0; j < 4; j++)
                    MMA16816F(acc[i][j], a[i], b[j]);
        }
    }

    // epilogue
    #pragma unroll
    for (int i = 0; i < 4; i++) {
        int mr = m0 + wm * 64 + i * 16 + (lane >> 2);
        #pragma unroll
        for (int j = 0; j < 4; j++) {
            int nc = n0 + wn * 32 + j * 8 + (lane & 3) * 2;
            float v0 = acc[i][j][0], v1 = acc[i][j][1];
            float v2 = acc[i][j][2], v3 = acc[i][j][3];
            if (mode == 1) {
                v0 = v0 / (1.f + expf(-v0));
                v1 = v1 / (1.f + expf(-v1));
                v2 = v2 / (1.f + expf(-v2));
                v3 = v3 / (1.f + expf(-v3));
            }
            *(float2*)&Cp[(size_t)mr * Dd + nc]       = make_float2(v0, v1);
            *(float2*)&Cp[(size_t)(mr + 8) * Dd + nc] = make_float2(v2, v3);
        }
    }
}

// =====================================================================
// Kernel A: token mixing
// =====================================================================
#define KA_SMEM ((4*2048 + 8*4*160 + 4*160 + 4*64) * 4)   // 56832 B

__global__ void __launch_bounds__(256) kA(
    const float* __restrict__ x,   const float* __restrict__ shift,
    const float* __restrict__ tmx, const float* __restrict__ tmw,
    const float* __restrict__ tmk, const float* __restrict__ tmv,
    const float* __restrict__ tmr, const float* __restrict__ tmg,
    const float* __restrict__ w1,  const float* __restrict__ w2,
    const float* __restrict__ td,  const float* __restrict__ dw1,
    const float* __restrict__ dw2)
{
    extern __shared__ float sm[];
    float* sxxx = sm;                       // 4*2048
    float* ps   = sm + 4 * 2048;            // 8*4*160
    float* sst  = ps + 8 * 4 * 160;         // 4*160
    float* ssh  = sst + 4 * 160;            // 4*64

    const int tid  = threadIdx.x;
    const int wqid = tid >> 5;
    const int lane = tid & 31;
    const int t0   = blockIdx.x * TOK;

    for (int tok = 0; tok < TOK; tok++) {
        int gt = t0 + tok;
        int b = gt / Tt, tt = gt % Tt;
        const float* xrow = x + (size_t)gt * Dd;
        const float* xprv = (tt == 0) ? (shift + (size_t)b * Dd)
                                      : (x + (size_t)(gt - 1) * Dd);
        for (int d = tid; d < Dd; d += 256) {
            float xv_ = xrow[d];
            sxxx[tok * Dd + d] = xv_ + (xprv[d] - xv_) * tmx[d];
        }
    }
    __syncthreads();

    {
        float acc[5][TOK];
        #pragma unroll
        for (int g = 0; g < 5; g++)
            #pragma unroll
            for (int t = 0; t < TOK; t++) acc[g][t] = 0.f;
        const int d0 = wqid * 256;
        for (int dd = 0; dd < 256; dd++) {
            int d = d0 + dd;
            float xv[TOK];
            #pragma unroll
            for (int t = 0; t < TOK; t++) xv[t] = sxxx[t * Dd + d];
            #pragma unroll
            for (int g = 0; g < 5; g++) {
                float w1v = w1[d * 160 + g * 32 + lane];
                #pragma unroll
                for (int t = 0; t < TOK; t++) acc[g][t] += xv[t] * w1v;
            }
        }
        #pragma unroll
        for (int g = 0; g < 5; g++)
            #pragma unroll
            for (int t = 0; t < TOK; t++)
                ps[(wqid * TOK + t) * 160 + g * 32 + lane] = acc[g][t];
        __syncthreads();
        for (int idx = tid; idx < TOK * 160; idx += 256) {
            int t = idx / 160, j = idx % 160;
            float s = 0.f;
            #pragma unroll
            for (int w8 = 0; w8 < 8; w8++) s += ps[(w8 * TOK + t) * 160 + j];
            sst[t * 160 + j] = tanhf(s);
        }
        __syncthreads();
    }

    for (int d = tid; d < Dd; d += 256) {
        float macc[TOK][5];
        #pragma unroll
        for (int t = 0; t < TOK; t++)
            #pragma unroll
            for (int g = 0; g < 5; g++) macc[t][g] = 0.f;

        #pragma unroll
        for (int g = 0; g < 5; g++) {
            for (int j32 = 0; j32 < 32; j32++) {
                int j = g * 32 + j32;
                float w2v = w2[(size_t)j * Dd + d];
                #pragma unroll
                for (int t = 0; t < TOK; t++) macc[t][g] += sst[t * 160 + j] * w2v;
            }
        }
        float twv = tmw[d], tkv = tmk[d], tvv = tmv[d], trv = tmr[d], tgv = tmg[d];
        #pragma unroll
        for (int tok = 0; tok < TOK; tok++) {
            int gt = t0 + tok;
            int b = gt / Tt, tt = gt % Tt;
            float xv_ = x[(size_t)gt * Dd + d];
            float xpv = (tt == 0) ? shift[(size_t)b * Dd + d]
                                  : x[(size_t)(gt - 1) * Dd + d];
            float dx = xpv - xv_;
            size_t o = (size_t)gt * Dd + d;
            split_fp16(xv_ + dx * (tkv + macc[tok][1]), g_xkh[o], g_xkl[o]);
            split_fp16(xv_ + dx * (tvv + macc[tok][2]), g_xvh[o], g_xvl[o]);
            split_fp16(xv_ + dx * (trv + macc[tok][3]), g_xrh[o], g_xrl[o]);
            split_fp16(xv_ + dx * (tgv + macc[tok][4]), g_xgh[o], g_xgl[o]);
            sxxx[tok * Dd + d] = xv_ + dx * (twv + macc[tok][0]);
        }
    }
    __syncthreads();

    {
        float acc[2][TOK];
        #pragma unroll
        for (int g = 0; g < 2; g++)
            #pragma unroll
            for (int t = 0; t < TOK; t++) acc[g][t] = 0.f;
        const int d0 = wqid * 256;
        for (int dd = 0; dd < 256; dd++) {
            int d = d0 + dd;
            float xv[TOK];
            #pragma unroll
            for (int t = 0; t < TOK; t++) xv[t] = sxxx[t * Dd + d];
            #pragma unroll
            for (int g = 0; g < 2; g++) {
                float w1v = dw1[d * 64 + g * 32 + lane];
                #pragma unroll
                for (int t = 0; t < TOK; t++) acc[g][t] += xv[t] * w1v;
            }
        }
        #pragma unroll
        for (int g = 0; g < 2; g++)
            #pragma unroll
            for (int t = 0; t < TOK; t++)
                ps[(wqid * TOK + t) * 64 + g * 32 + lane] = acc[g][t];
        __syncthreads();
        for (int idx = tid; idx < TOK * 64; idx += 256) {
            int t = idx / 64, j = idx % 64;
            float s = 0.f;
            #pragma unroll
            for (int w8 = 0; w8 < 8; w8++) s += ps[(w8 * TOK + t) * 64 + j];
            ssh[t * 64 + j] = tanhf(s);
        }
        __syncthreads();
    }

    for (int d = tid; d < Dd; d += 256) {
        float acc[TOK];
        #pragma unroll
        for (int t = 0; t < TOK; t++) acc[t] = 0.f;
        for (int j = 0; j < 64; j++) {
            float w2v = dw2[(size_t)j * Dd + d];
            #pragma unroll
            for (int t = 0; t < TOK; t++) acc[t] += ssh[t * 64 + j] * w2v;
        }
        float tdv = td[d];
        #pragma unroll
        for (int t = 0; t < TOK; t++) {
            float wdv = fmaxf(expf(-expf(tdv + acc[t])), 0.005f);
            g_wd[(size_t)(t0 + t) * Dd + d] = wdv;
        }
    }
}

// =====================================================================
// Weight convert: fp32 -> fp16 (hi only), all 5 in one launch
// =====================================================================
struct ConvArgs {
    const float* s[5];
    __half* h[5];
};

__global__ void __launch_bounds__(256) wconv_all(ConvArgs ca)
{
    const int z = blockIdx.y;
    const float* src = ca.s[z];
    __half* hi = ca.h[z];
    int i = (blockIdx.x * 256 + threadIdx.x) * 4;
    float4 v = *(const float4*)(src + i);
    __half2* hp = (__half2*)(hi + i);
    hp[0] = __floats2half2_rn(v.x, v.y);
    hp[1] = __floats2half2_rn(v.z, v.w);
}

// =====================================================================
// WKV pass 1
// =====================================================================
__global__ void __launch_bounds__(64) wkv_pass1(
    const float* __restrict__ kbuf, const float* __restrict__ vbuf)
{
    const int cid = blockIdx.x;
    const int n  = cid % NCH;
    const int bh = cid / NCH;
    const int h  = bh % Hh;
    const int b  = bh / Hh;
    const int j  = threadIdx.x;

    __shared__ float2 sp[64];
    float S[64];
    #pragma unroll
    for (int k = 0; k < 64; k++) S[k] = 0.f;
    float wsa = 1.f;

    size_t base = ((size_t)(b * Tt + n * CH)) * Dd + h * 64;
    for (int tt = 0; tt < CH; tt++) {
        size_t o = base + (size_t)tt * Dd;
        float kk = kbuf[o + j];
        float wd = g_wd[o + j];
        float vj = vbuf[o + j];
        sp[j] = make_float2(kk, wd);
        wsa *= wd;
        __syncthreads();
        const float4* p4 = (const float4*)sp;
        #pragma unroll
        for (int kq = 0; kq < 32; kq++) {
            float4 q = p4[kq];
            S[2 * kq]     = q.y * S[2 * kq]     + q.x * vj;
            S[2 * kq + 1] = q.w * S[2 * kq + 1] + q.z * vj;
        }
        __syncthreads();
    }
    float* cs = g_cs + (size_t)cid * 4096;
    #pragma unroll
    for (int k = 0; k < 64; k++) cs[k * 64 + j] = S[k];
    g_ws[cid * 64 + j] = wsa;
}

// =====================================================================
// WKV pass 2
// =====================================================================
__global__ void __launch_bounds__(64) wkv_pass2(
    const float* __restrict__ state0, float* __restrict__ out_state)
{
    const int bh = blockIdx.x;
    const int j  = threadIdx.x;
    __shared__ float sws[64];

    float S[64];
    const float* s0 = state0 + (size_t)bh * 4096;
    #pragma unroll
    for (int k = 0; k < 64; k++) S[k] = s0[k * 64 + j];

    for (int n = 0; n < NCH; n++) {
        size_t cid = (size_t)bh * NCH + n;
        float* es = g_es + cid * 4096;
        #pragma unroll
        for (int k = 0; k < 64; k++) es[k * 64 + j] = S[k];
        sws[j] = g_ws[cid * 64 + j];
        __syncthreads();
        const float* cs = g_cs + cid * 4096;
        #pragma unroll
        for (int k = 0; k < 64; k++)
            S[k] = S[k] * sws[k] + cs[k * 64 + j];
        __syncthreads();
    }
    float* os = out_state + (size_t)bh * 4096;
    #pragma unroll
    for (int k = 0; k < 64; k++) os[k * 64 + j] = S[k];
}

// =====================================================================
// WKV pass 3
// =====================================================================
__global__ void __launch_bounds__(64) wkv_pass3(
    const float* __restrict__ rbuf, const float* __restrict__ kbuf,
    const float* __restrict__ vbuf, const float* __restrict__ faaaa)
{
    const int cid = blockIdx.x;
    const int n  = cid % NCH;
    const int bh = cid / NCH;
    const int h  = bh % Hh;
    const int b  = bh / Hh;
    const int j  = threadIdx.x;

    __shared__ float4 sq[64];
    float S[64];
    const float* es = g_es + (size_t)cid * 4096;
    #pragma unroll
    for (int k = 0; k < 64; k++) S[k] = es[k * 64 + j];
    const float uj = faaaa[h * 64 + j];

    size_t base = ((size_t)(b * Tt + n * CH)) * Dd + h * 64;
    for (int tt = 0; tt < CH; tt++) {
        size_t o = base + (size_t)tt * Dd;
        float kk = kbuf[o + j];
        float wd = g_wd[o + j];
        float rr = rbuf[o + j];
        float vj = vbuf[o + j];
        sq[j] = make_float4(kk, wd, rr, rr * uj * kk);
        __syncthreads();
        float outv = 0.f, rk = 0.f;
        #pragma unroll
        for (int k = 0; k < 64; k++) {
            float4 q = sq[k];
            outv += q.z * S[k];
            rk   += q.w;
            S[k] = q.y * S[k] + q.x * vj;
        }
        g_xout[o + j] = outv + rk * vj;
        __syncthreads();
    }
}

// =====================================================================
// GroupNorm * silu-gate -> fp16 hi/lo
// =====================================================================
__global__ void __launch_bounds__(256) gn_gate(
    const float* __restrict__ gamma, const float* __restrict__ beta)
{
    const int token = blockIdx.x;
    const int w = threadIdx.x >> 5;
    const int lane = threadIdx.x & 31;

    for (int gq = 0; gq < 4; gq++) {
        int h = w * 4 + gq;
        size_t base = (size_t)token * Dd + h * 64;
        float v0 = g_xout[base + lane];
        float v1 = g_xout[base + 32 + lane];
        float s  = v0 + v1;
        float s2 = v0 * v0 + v1 * v1;
        #pragma unroll
        for (int off = 16; off > 0; off >>= 1) {
            s  += __shfl_xor_sync(0xffffffffu, s,  off);
            s2 += __shfl_xor_sync(0xffffffffu, s2, off);
        }
        float mu  = s * (1.f / 64.f);
        float var = s2 * (1.f / 64.f) - mu * mu;
        float inv = rsqrtf(var + EPSV);
        int d0 = h * 64 + lane;
        float y0 = ((v0 - mu) * inv * gamma[d0]      + beta[d0])      * g_g[base + lane];
        float y1 = ((v1 - mu) * inv * gamma[d0 + 32] + beta[d0 + 32]) * g_g[base + 32 + lane];
        split_fp16(y0, g_yh[base + lane],      g_yl[base + lane]);
        split_fp16(y1, g_yh[base + 32 + lane], g_yl[base + 32 + lane]);
    }
}

__global__ void __launch_bounds__(256) xlast_copy(
    const float* __restrict__ x, float* __restrict__ dst)
{
    int i = blockIdx.x * 256 + threadIdx.x;
    int b = i / Dd, d = i % Dd;
    dst[i] = x[((size_t)b * Tt + Tt - 1) * Dd + d];
}

// =====================================================================
// launch
// =====================================================================
extern "C" void kernel_launch(void* const* d_in, const int* in_sizes, int n_in,
                              void* d_out, int out_size)
{
    const float* x      = (const float*)d_in[0];
    const float* shift  = (const float*)d_in[1];
    const float* state0 = (const float*)d_in[2];
    const float* tmx    = (const float*)d_in[3];
    const float* tmw    = (const float*)d_in[4];
    const float* tmk    = (const float*)d_in[5];
    const float* tmv    = (const float*)d_in[6];
    const float* tmr    = (const float*)d_in[7];
    const float* tmg    = (const float*)d_in[8];
    const float* w1     = (const float*)d_in[9];
    const float* w2     = (const float*)d_in[10];
    const float* td     = (const float*)d_in[11];
    const float* dw1    = (const float*)d_in[12];
    const float* dw2    = (const float*)d_in[13];
    const float* faaaa  = (const float*)d_in[14];
    const float* Wr     = (const float*)d_in[15];
    const float* Wk     = (const float*)d_in[16];
    const float* Wv     = (const float*)d_in[17];
    const float* Wg     = (const float*)d_in[18];
    const float* Wo     = (const float*)d_in[19];
    const float* gamma  = (const float*)d_in[20];
    const float* beta   = (const float*)d_in[21];
    float* out = (float*)d_out;

    __half *xkh,*xkl,*xvh,*xvl,*xrh,*xrl,*xgh,*xgl,*yh,*yl;
    __half *Wrh,*Wkh,*Wvh,*Wgh,*Woh;
    float *rb,*kb,*vb,*gb;
    cudaGetSymbolAddress((void**)&xkh, g_xkh); cudaGetSymbolAddress((void**)&xkl, g_xkl);
    cudaGetSymbolAddress((void**)&xvh, g_xvh); cudaGetSymbolAddress((void**)&xvl, g_xvl);
    cudaGetSymbolAddress((void**)&xrh, g_xrh); cudaGetSymbolAddress((void**)&xrl, g_xrl);
    cudaGetSymbolAddress((void**)&xgh, g_xgh); cudaGetSymbolAddress((void**)&xgl, g_xgl);
    cudaGetSymbolAddress((void**)&yh,  g_yh);  cudaGetSymbolAddress((void**)&yl,  g_yl);
    cudaGetSymbolAddress((void**)&Wrh, g_Wrh);
    cudaGetSymbolAddress((void**)&Wkh, g_Wkh);
    cudaGetSymbolAddress((void**)&Wvh, g_Wvh);
    cudaGetSymbolAddress((void**)&Wgh, g_Wgh);
    cudaGetSymbolAddress((void**)&Woh, g_Woh);
    cudaGetSymbolAddress((void**)&rb, g_r);
    cudaGetSymbolAddress((void**)&kb, g_k);
    cudaGetSymbolAddress((void**)&vb, g_v);
    cudaGetSymbolAddress((void**)&gb, g_g);

    const size_t BTD = (size_t)BT * Dd;

    cudaFuncSetAttribute(gemm4, cudaFuncAttributeMaxDynamicSharedMemorySize, G_SMEM);
    cudaFuncSetAttribute(kA,    cudaFuncAttributeMaxDynamicSharedMemorySize, KA_SMEM);

    // ---- 0: weight convert (all 5) ----
    ConvArgs ca;
    ca.s[0] = Wr; ca.h[0] = Wrh;
    ca.s[1] = Wk; ca.h[1] = Wkh;
    ca.s[2] = Wv; ca.h[2] = Wvh;
    ca.s[3] = Wg; ca.h[3] = Wgh;
    ca.s[4] = Wo; ca.h[4] = Woh;
    dim3 wsg((Dd * Dd) / (256 * 4), 5);
    wconv_all<<<wsg, 256>>>(ca);

    // ---- 1: token mixing ----
    kA<<<BT / TOK, 256, KA_SMEM>>>(x, shift, tmx, tmw, tmk, tmv, tmr, tmg,
                                   w1, w2, td, dw1, dw2);

    // ---- 2: x last ----
    xlast_copy<<<(Bb * Dd) / 256, 256>>>(x, out + BTD);

    // ---- 3,4: projection GEMMs (2 x 2 batched) ----
    GemmArgs g1;
    g1.Ah[0] = xrh; g1.Al[0] = xrl; g1.Wh[0] = Wrh; g1.C[0] = rb; g1.mode[0] = 0;
    g1.Ah[1] = xkh; g1.Al[1] = xkl; g1.Wh[1] = Wkh; g1.C[1] = kb; g1.mode[1] = 0;
    GemmArgs g2;
    g2.Ah[0] = xvh; g2.Al[0] = xvl; g2.Wh[0] = Wvh; g2.C[0] = vb; g2.mode[0] = 0;
    g2.Ah[1] = xgh; g2.Al[1] = xgl; g2.Wh[1] = Wgh; g2.C[1] = gb; g2.mode[1] = 1;
    dim3 gg(Dd / 128, BT / 128, 2);
    gemm4<<<gg, 256, G_SMEM>>>(g1);
    gemm4<<<gg, 256, G_SMEM>>>(g2);

    // ---- 5,6,7: WKV ----
    wkv_pass1<<<Bb * Hh * NCH, 64>>>(kb, vb);
    wkv_pass2<<<Bb * Hh, 64>>>(state0, out + BTD + (size_t)Bb * Dd);
    wkv_pass3<<<Bb * Hh * NCH, 64>>>(rb, kb, vb, faaaa);

    // ---- 8: groupnorm * gate ----
    gn_gate<<<BT, 256>>>(gamma, beta);

    // ---- 9: output GEMM ----
    GemmArgs g3;
    g3.Ah[0] = yh; g3.Al[0] = yl; g3.Wh[0] = Woh; g3.C[0] = out; g3.mode[0] = 0;
    dim3 go(Dd / 128, BT / 128, 1);
    gemm4<<<go, 256, G_SMEM>>>(g3);
}